// round 9
// baseline (speedup 1.0000x reference)
#include <cuda_runtime.h>
#include <cuda_bf16.h>
#include <math.h>
#include <cstdint>

// Problem constants
#define BB 2
#define SS 2048
#define DD 2048
#define HH 16
#define HD 128
#define TOPK 256
#define HIDDEN 8192
#define RSEL (BB*TOPK)      // 512 selected rows total
#define RTOT (RSEL + BB)    // + 1 shared row per batch = 514
#define EPS 1e-6f
#define QMAXF 32512.0f

// ---------------- scratch (static device globals; no allocs allowed) ----------------
__device__ float g_tw[BB*SS];
__device__ int   g_idx[BB*TOPK];
__device__ int   g_rank[BB*SS];
__device__ float g_xn[RSEL*DD];
__device__ float g_q[RSEL*DD];
__device__ float g_k[RSEL*DD];
__device__ float g_v[RSEL*DD];
__device__ float g_attn[RTOT*DD];
__device__ float g_h[RTOT*DD];
__device__ float g_hn[RTOT*DD];
__device__ float g_u1[RTOT*HIDDEN];
__device__ float g_u3[RTOT*HIDDEN];
__device__ float g_outrows[RTOT*DD];
// int8 quant buffers
__device__ int8_t g_qa1[RTOT*HIDDEN];
__device__ int8_t g_qa0[RTOT*HIDDEN];
__device__ float  g_da[RTOT];
__device__ int8_t g_qkv1[3*DD*DD];
__device__ int8_t g_qkv0[3*DD*DD];
__device__ float  g_dqkv[3*DD];
__device__ int8_t g_qo1[DD*DD];
__device__ int8_t g_qo0[DD*DD];
__device__ float  g_do[DD];
__device__ int8_t g_q13_1[2u*DD*HIDDEN];
__device__ int8_t g_q13_0[2u*DD*HIDDEN];
__device__ float  g_d13[2*HIDDEN];
__device__ int8_t g_q2_1[DD*HIDDEN];
__device__ int8_t g_q2_0[DD*HIDDEN];
__device__ float  g_d2[DD];

// ================= helpers =================
__device__ __forceinline__ uint32_t smem_u32(const void* p) {
    uint32_t a;
    asm("{ .reg .u64 t; cvta.to.shared.u64 t, %1; cvt.u32.u64 %0, t; }" : "=r"(a) : "l"(p));
    return a;
}
__device__ __forceinline__ void cpa16(uint32_t dst, const void* src, int sz) {
    asm volatile("cp.async.cg.shared.global [%0], [%1], 16, %2;" :: "r"(dst), "l"(src), "r"(sz) : "memory");
}
#define CP_COMMIT() asm volatile("cp.async.commit_group;" ::: "memory")

__device__ __forceinline__ void mma_s8(int* cc, const uint32_t* a, const uint32_t* b) {
    asm volatile(
        "mma.sync.aligned.m16n8k32.row.col.s32.s8.s8.s32 "
        "{%0,%1,%2,%3},{%4,%5,%6,%7},{%8,%9},{%0,%1,%2,%3};"
        : "+r"(cc[0]), "+r"(cc[1]), "+r"(cc[2]), "+r"(cc[3])
        : "r"(a[0]), "r"(a[1]), "r"(a[2]), "r"(a[3]), "r"(b[0]), "r"(b[1]));
}

// quantize one float to split int8 pair given scale (= QMAXF/max)
__device__ __forceinline__ void q_split(float f, float s, int& hi, int& lo) {
    int q = __float2int_rn(f * s);
    q = max(-32639, min(32639, q));
    hi = (q + 128) >> 8;          // [-127,127]
    lo = q - (hi << 8);           // [-128,127]
}

// ================= quantization kernels =================
// per-row quant of activations A[M][K] -> qa1,qa0 [M][K], da[row]=max/QMAX
__global__ void quantA_kernel(const float* __restrict__ A, int8_t* __restrict__ q1,
                              int8_t* __restrict__ q0, float* __restrict__ da, int K) {
    int row = blockIdx.x;
    const float* ar = A + (size_t)row * K;
    __shared__ float red[256];
    float m = 0.f;
    for (int c = threadIdx.x; c < K; c += 256) m = fmaxf(m, fabsf(ar[c]));
    red[threadIdx.x] = m; __syncthreads();
    for (int o = 128; o > 0; o >>= 1) {
        if (threadIdx.x < o) red[threadIdx.x] = fmaxf(red[threadIdx.x], red[threadIdx.x + o]);
        __syncthreads();
    }
    float mx = red[0];
    float s = (mx > 0.f) ? (QMAXF / mx) : 0.f;
    if (threadIdx.x == 0) da[row] = mx * (1.f / QMAXF);
    int8_t* q1r = q1 + (size_t)row * K;
    int8_t* q0r = q0 + (size_t)row * K;
    for (int c4 = threadIdx.x * 4; c4 < K; c4 += 1024) {
        float4 v = *(const float4*)(ar + c4);
        uint32_t b1 = 0, b0 = 0;
        const float* vp = &v.x;
        #pragma unroll
        for (int j = 0; j < 4; j++) {
            int hi, lo; q_split(vp[j], s, hi, lo);
            b1 |= ((uint32_t)(uint8_t)(int8_t)hi) << (8 * j);
            b0 |= ((uint32_t)(uint8_t)(int8_t)lo) << (8 * j);
        }
        *(uint32_t*)(q1r + c4) = b1;
        *(uint32_t*)(q0r + c4) = b0;
    }
}

// per-col max of weight W[K][N] -> dcol[n] = max/QMAX.  block = 64 cols x 4 k-lanes
__global__ void colmax_kernel(const float* __restrict__ W, float* __restrict__ dcol, int K, int N) {
    int n0 = blockIdx.x * 64;
    int nn = threadIdx.x & 63, kl = threadIdx.x >> 6;
    float m = 0.f;
    for (int k = kl; k < K; k += 4) m = fmaxf(m, fabsf(W[(size_t)k * N + n0 + nn]));
    __shared__ float red[256];
    red[threadIdx.x] = m; __syncthreads();
    if (kl == 0) {
        float mm = fmaxf(fmaxf(red[nn], red[nn + 64]), fmaxf(red[nn + 128], red[nn + 192]));
        dcol[n0 + nn] = mm * (1.f / QMAXF);
    }
}

// quantize + transpose weight W[K][N] -> q1,q0 [N][K]
__global__ void quantB_kernel(const float* __restrict__ W, const float* __restrict__ dcol,
                              int8_t* __restrict__ q1, int8_t* __restrict__ q0, int K, int N) {
    __shared__ float ts[64][65];
    int t = threadIdx.x;
    int n0 = blockIdx.x * 64, k0 = blockIdx.y * 64;
    #pragma unroll
    for (int i = 0; i < 16; i++) {
        int idx = t + 256 * i;
        int kk = idx >> 6, nn = idx & 63;
        ts[kk][nn] = W[(size_t)(k0 + kk) * N + n0 + nn];
    }
    __syncthreads();
    int j = t >> 2, ch = t & 3;
    int n = n0 + j;
    float d = dcol[n];
    float s = (d > 0.f) ? (1.f / d) : 0.f;
    uint32_t w1p[4] = {0,0,0,0}, w0p[4] = {0,0,0,0};
    #pragma unroll
    for (int e = 0; e < 16; e++) {
        float f = ts[ch * 16 + e][j];
        int hi, lo; q_split(f, s, hi, lo);
        int word = e >> 2, sh = (e & 3) * 8;
        w1p[word] |= ((uint32_t)(uint8_t)(int8_t)hi) << sh;
        w0p[word] |= ((uint32_t)(uint8_t)(int8_t)lo) << sh;
    }
    int4 v1 = make_int4((int)w1p[0], (int)w1p[1], (int)w1p[2], (int)w1p[3]);
    int4 v0 = make_int4((int)w0p[0], (int)w0p[1], (int)w0p[2], (int)w0p[3]);
    *(int4*)(q1 + (size_t)n * K + k0 + ch * 16) = v1;
    *(int4*)(q0 + (size_t)n * K + k0 + ch * 16) = v0;
}

// ================= int8 split GEMM: C[M,N] = A @ B  (A [M][K] s8 pairs, B [N][K] s8 pairs) =================
#define IBM 128
#define IBN 128
#define IBK 64
#define ISTAGE 32768            // bytes per stage: A1 8K, A0 8K, B1 8K, B0 8K
#define I8_SMEM (2*ISTAGE)

// swizzled offset within an 8KB part: rows of 64B, 16B units XOR'd by (row>>1)&3
__device__ __forceinline__ uint32_t swzoff(int row, int off) {
    return (uint32_t)(row * 64 + ((((off >> 4) ^ ((row >> 1) & 3)) << 4) | (off & 15)));
}

__device__ __forceinline__ void i8_load_stage(
    const int8_t* __restrict__ qa1, const int8_t* __restrict__ qa0,
    const int8_t* __restrict__ b1p, const int8_t* __restrict__ b0p,
    uint32_t sbase, int buf, int bm, int bn, int k0, int M, int K, int tid)
{
    uint32_t st = sbase + (uint32_t)buf * ISTAGE;
    #pragma unroll
    for (int i = 0; i < 2; i++) {
        int g = tid + 256 * i;
        int row = g >> 2, u = g & 3;
        int gm = bm + row;
        int sz = (gm < M) ? 16 : 0;
        int gmc = (gm < M) ? gm : (M - 1);
        size_t goff = (size_t)gmc * K + k0 + u * 16;
        uint32_t doff = (uint32_t)(row * 64 + ((u ^ ((row >> 1) & 3)) << 4));
        cpa16(st + doff,          qa1 + goff, sz);
        cpa16(st + 8192u + doff,  qa0 + goff, sz);
    }
    #pragma unroll
    for (int i = 0; i < 2; i++) {
        int g = tid + 256 * i;
        int n = g >> 2, u = g & 3;
        size_t goff = (size_t)(bn + n) * K + k0 + u * 16;
        uint32_t doff = (uint32_t)(n * 64 + ((u ^ ((n >> 1) & 3)) << 4));
        cpa16(st + 16384u + doff, b1p + goff, 16);
        cpa16(st + 24576u + doff, b0p + goff, 16);
    }
    CP_COMMIT();
}

__global__ void __launch_bounds__(256, 1) i8_gemm(
    const int8_t* __restrict__ qa1, const int8_t* __restrict__ qa0, const float* __restrict__ da,
    const int8_t* __restrict__ qb1, const int8_t* __restrict__ qb0, const float* __restrict__ db,
    float* C0c, float* C1c, float* C2c, int M, int K, int N)
{
    extern __shared__ char sm8[];
    float* C = (blockIdx.z == 0) ? C0c : ((blockIdx.z == 1) ? C1c : C2c);
    const int8_t* b1p = qb1 + (size_t)blockIdx.z * N * K;
    const int8_t* b0p = qb0 + (size_t)blockIdx.z * N * K;
    const float* dbp = db + (size_t)blockIdx.z * N;
    uint32_t sbase = smem_u32(sm8);
    int tid = threadIdx.x;
    int bm = blockIdx.y * IBM, bn = blockIdx.x * IBN;
    int lane = tid & 31, wid = tid >> 5;
    int r = lane >> 2, c = lane & 3;
    int m_base = (wid >> 2) * 64;    // 0 or 64
    int n_base = (wid & 3) * 32;     // 0,32,64,96

    int acch[4][4][4], accm[4][4][4];
    #pragma unroll
    for (int mt = 0; mt < 4; mt++)
        #pragma unroll
        for (int nt = 0; nt < 4; nt++)
            #pragma unroll
            for (int q = 0; q < 4; q++) { acch[mt][nt][q] = 0; accm[mt][nt][q] = 0; }

    int T = K / IBK;
    i8_load_stage(qa1, qa0, b1p, b0p, sbase, 0, bm, bn, 0, M, K, tid);

    for (int i = 0; i < T; i++) {
        int buf = i & 1;
        if (i + 1 < T) {
            i8_load_stage(qa1, qa0, b1p, b0p, sbase, buf ^ 1, bm, bn, (i + 1) * IBK, M, K, tid);
            asm volatile("cp.async.wait_group 1;" ::: "memory");
        } else {
            asm volatile("cp.async.wait_group 0;" ::: "memory");
        }
        __syncthreads();

        const char* sA1 = sm8 + buf * ISTAGE;
        const char* sA0 = sA1 + 8192;
        const char* sB1 = sA1 + 16384;
        const char* sB0 = sA1 + 24576;
        #pragma unroll
        for (int ks = 0; ks < 2; ks++) {
            int o1 = ks * 32 + 4 * c;
            uint32_t a1f[4][4], a0f[4][4];
            #pragma unroll
            for (int mt = 0; mt < 4; mt++) {
                int row0 = m_base + mt * 16 + r;
                a1f[mt][0] = *(const uint32_t*)(sA1 + swzoff(row0,     o1));
                a1f[mt][1] = *(const uint32_t*)(sA1 + swzoff(row0 + 8, o1));
                a1f[mt][2] = *(const uint32_t*)(sA1 + swzoff(row0,     o1 + 16));
                a1f[mt][3] = *(const uint32_t*)(sA1 + swzoff(row0 + 8, o1 + 16));
                a0f[mt][0] = *(const uint32_t*)(sA0 + swzoff(row0,     o1));
                a0f[mt][1] = *(const uint32_t*)(sA0 + swzoff(row0 + 8, o1));
                a0f[mt][2] = *(const uint32_t*)(sA0 + swzoff(row0,     o1 + 16));
                a0f[mt][3] = *(const uint32_t*)(sA0 + swzoff(row0 + 8, o1 + 16));
            }
            uint32_t b1f[4][2], b0f[4][2];
            #pragma unroll
            for (int nt = 0; nt < 4; nt++) {
                int n = n_base + nt * 8 + r;
                b1f[nt][0] = *(const uint32_t*)(sB1 + swzoff(n, o1));
                b1f[nt][1] = *(const uint32_t*)(sB1 + swzoff(n, o1 + 16));
                b0f[nt][0] = *(const uint32_t*)(sB0 + swzoff(n, o1));
                b0f[nt][1] = *(const uint32_t*)(sB0 + swzoff(n, o1 + 16));
            }
            #pragma unroll
            for (int mt = 0; mt < 4; mt++)
                #pragma unroll
                for (int nt = 0; nt < 4; nt++) {
                    mma_s8(acch[mt][nt], a1f[mt], b1f[nt]);
                    mma_s8(accm[mt][nt], a1f[mt], b0f[nt]);
                    mma_s8(accm[mt][nt], a0f[mt], b1f[nt]);
                }
        }
        __syncthreads();
    }

    // epilogue: C = (65536*hh + 256*mx) * da[row] * db[col]
    #pragma unroll
    for (int mt = 0; mt < 4; mt++) {
        int row0 = bm + m_base + mt * 16 + r;
        float da0 = (row0 < M) ? da[row0] : 0.f;
        float da1 = (row0 + 8 < M) ? da[row0 + 8] : 0.f;
        #pragma unroll
        for (int nt = 0; nt < 4; nt++) {
            int col = bn + n_base + nt * 8 + c * 2;
            float db0 = dbp[col], db1 = dbp[col + 1];
            if (row0 < M) {
                float v0 = fmaf(65536.f, (float)acch[mt][nt][0], 256.f * (float)accm[mt][nt][0]) * da0 * db0;
                float v1 = fmaf(65536.f, (float)acch[mt][nt][1], 256.f * (float)accm[mt][nt][1]) * da0 * db1;
                *(float2*)(C + (size_t)row0 * N + col) = make_float2(v0, v1);
            }
            if (row0 + 8 < M) {
                float v2 = fmaf(65536.f, (float)acch[mt][nt][2], 256.f * (float)accm[mt][nt][2]) * da1 * db0;
                float v3 = fmaf(65536.f, (float)acch[mt][nt][3], 256.f * (float)accm[mt][nt][3]) * da1 * db1;
                *(float2*)(C + (size_t)(row0 + 8) * N + col) = make_float2(v2, v3);
            }
        }
    }
}

// ---------------- 1. router ----------------
__global__ void router_kernel(const float* __restrict__ x, const float* __restrict__ rw,
                              float* __restrict__ tw, float* __restrict__ dout,
                              size_t off_tw, size_t out_size) {
    int tok = blockIdx.x;
    __shared__ float red[256];
    float s = 0.f;
    const float* xr = x + (size_t)tok * DD;
    for (int c = threadIdx.x; c < DD; c += 256) s += xr[c] * rw[c];
    red[threadIdx.x] = s; __syncthreads();
    for (int o = 128; o > 0; o >>= 1) {
        if (threadIdx.x < o) red[threadIdx.x] += red[threadIdx.x + o];
        __syncthreads();
    }
    if (threadIdx.x == 0) {
        tw[tok] = red[0];
        if (off_tw + (size_t)tok < out_size) dout[off_tw + tok] = red[0];
    }
}

// ---------------- 2. top-k ----------------
__global__ void topk_kernel(const float* __restrict__ tw, int* __restrict__ gidx,
                            float* __restrict__ dout, size_t off_idx, size_t out_size) {
    __shared__ float v[SS];
    __shared__ int   id[SS];
    int b = blockIdx.x;
    int t = threadIdx.x;
    for (int i = t; i < SS; i += 1024) { v[i] = tw[b*SS + i]; id[i] = i; }
    __syncthreads();
    for (int k = 2; k <= SS; k <<= 1) {
        for (int j = k >> 1; j > 0; j >>= 1) {
            for (int i = t; i < SS; i += 1024) {
                int ixj = i ^ j;
                if (ixj > i) {
                    bool up = ((i & k) == 0);
                    float va = v[i], vb = v[ixj];
                    int   ia = id[i], ib = id[ixj];
                    bool aBeforeB = (va > vb) || (va == vb && ia < ib);
                    bool sw = up ? !aBeforeB : aBeforeB;
                    if (sw) { v[i]=vb; v[ixj]=va; id[i]=ib; id[ixj]=ia; }
                }
            }
            __syncthreads();
        }
    }
    for (int i = t; i < TOPK; i += 1024) {
        gidx[b*TOPK + i] = id[i];
        size_t o = off_idx + (size_t)b*TOPK + i;
        if (o < out_size) dout[o] = (float)id[i];
    }
}

// ---------------- 3. rank map ----------------
__global__ void rank_init(int* __restrict__ rank) {
    int i = blockIdx.x*256 + threadIdx.x;
    if (i < BB*SS) rank[i] = -1;
}
__global__ void rank_set(const int* __restrict__ gidx, int* __restrict__ rank) {
    int r = blockIdx.x*256 + threadIdx.x;
    if (r < RSEL) {
        int b = r / TOPK;
        rank[b*SS + gidx[r]] = r % TOPK;
    }
}

// ---------------- 4. gather + rmsnorm ----------------
__global__ void rmsnorm_gather(const float* __restrict__ x, const int* __restrict__ gidx,
                               const float* __restrict__ w, float* __restrict__ out) {
    int r = blockIdx.x;
    int b = r / TOPK;
    int pos = gidx[r];
    const float* xr = x + ((size_t)b*SS + pos) * DD;
    __shared__ float red[256];
    float s = 0.f;
    for (int c = threadIdx.x; c < DD; c += 256) { float v = xr[c]; s += v*v; }
    red[threadIdx.x] = s; __syncthreads();
    for (int o = 128; o > 0; o >>= 1) {
        if (threadIdx.x < o) red[threadIdx.x] += red[threadIdx.x + o];
        __syncthreads();
    }
    float rms = rsqrtf(red[0] / (float)DD + EPS);
    float* orow = out + (size_t)r * DD;
    for (int c = threadIdx.x; c < DD; c += 256) orow[c] = xr[c] * rms * w[c];
}

__global__ void rmsnorm_rows(const float* __restrict__ in, const float* __restrict__ w,
                             float* __restrict__ out) {
    int r = blockIdx.x;
    const float* xr = in + (size_t)r * DD;
    __shared__ float red[256];
    float s = 0.f;
    for (int c = threadIdx.x; c < DD; c += 256) { float v = xr[c]; s += v*v; }
    red[threadIdx.x] = s; __syncthreads();
    for (int o = 128; o > 0; o >>= 1) {
        if (threadIdx.x < o) red[threadIdx.x] += red[threadIdx.x + o];
        __syncthreads();
    }
    float rms = rsqrtf(red[0] / (float)DD + EPS);
    float* orow = out + (size_t)r * DD;
    for (int c = threadIdx.x; c < DD; c += 256) orow[c] = xr[c] * rms * w[c];
}

// ---------------- 6. rotary ----------------
__global__ void rotary_kernel(float* __restrict__ q, float* __restrict__ k,
                              const int* __restrict__ gidx, const float* __restrict__ freqs,
                              const int* __restrict__ startp) {
    int r = blockIdx.x;
    int pos = startp[0] + gidx[r];
    const float* f = freqs + (size_t)pos * HD;
    size_t base = (size_t)r * DD;
    for (int e = threadIdx.x; e < HH*HD/2; e += 256) {
        int hp = e & 63;
        float c = f[hp*2], sn = f[hp*2+1];
        size_t i0 = base + (size_t)e*2;
        float q0 = q[i0], q1 = q[i0+1];
        q[i0]   = q0*c - q1*sn;
        q[i0+1] = q0*sn + q1*c;
        float k0 = k[i0], k1 = k[i0+1];
        k[i0]   = k0*c - k1*sn;
        k[i0+1] = k0*sn + k1*c;
    }
}

// ---------------- 7. attention ----------------
#define QT 64
#define KC 64
#define QS_STRIDE 129
#define SC_STRIDE 257
__global__ void attn_kernel(const float* __restrict__ q, const float* __restrict__ k,
                            const float* __restrict__ v, float* __restrict__ attn) {
    extern __shared__ float smf[];
    float* qs = smf;
    float* kt = qs + QT*QS_STRIDE;
    float* sc = kt + KC*QS_STRIDE;
    int qt = blockIdx.x, h = blockIdx.y, b = blockIdx.z;
    int t = threadIdx.x;
    int rb = b * TOPK;
    for (int l = t; l < QT*HD; l += 256) {
        int qi = l / HD, d = l % HD;
        qs[qi*QS_STRIDE + d] = q[((size_t)(rb + qt*QT + qi))*DD + h*HD + d];
    }
    const float scale = 0.08838834764831845f;
    int qi = t >> 2;
    {
        int kj0 = (t & 3) * 16;
        for (int kc = 0; kc < TOPK/KC; kc++) {
            __syncthreads();
            for (int l = t; l < KC*HD; l += 256) {
                int kj = l / HD, d = l % HD;
                kt[kj*QS_STRIDE + d] = k[((size_t)(rb + kc*KC + kj))*DD + h*HD + d];
            }
            __syncthreads();
            float acc[16];
            #pragma unroll
            for (int n = 0; n < 16; n++) acc[n] = 0.f;
            for (int d = 0; d < HD; d++) {
                float qv = qs[qi*QS_STRIDE + d];
                #pragma unroll
                for (int n = 0; n < 16; n++)
                    acc[n] += qv * kt[(kj0+n)*QS_STRIDE + d];
            }
            #pragma unroll
            for (int n = 0; n < 16; n++)
                sc[qi*SC_STRIDE + kc*KC + kj0 + n] = acc[n] * scale;
        }
    }
    __syncthreads();
    if (t < QT) {
        float m = -1e30f;
        for (int j = 0; j < TOPK; j++) m = fmaxf(m, sc[t*SC_STRIDE + j]);
        float s = 0.f;
        for (int j = 0; j < TOPK; j++) {
            float e = expf(sc[t*SC_STRIDE + j] - m);
            sc[t*SC_STRIDE + j] = e; s += e;
        }
        float inv = 1.f / s;
        for (int j = 0; j < TOPK; j++) sc[t*SC_STRIDE + j] *= inv;
    }
    __syncthreads();
    int d0 = (t & 3) * 32;
    float oacc[32];
    #pragma unroll
    for (int i = 0; i < 32; i++) oacc[i] = 0.f;
    for (int kc = 0; kc < TOPK/KC; kc++) {
        __syncthreads();
        for (int l = t; l < KC*HD; l += 256) {
            int kj = l / HD, d = l % HD;
            kt[kj*QS_STRIDE + d] = v[((size_t)(rb + kc*KC + kj))*DD + h*HD + d];
        }
        __syncthreads();
        for (int j = 0; j < KC; j++) {
            float p = sc[qi*SC_STRIDE + kc*KC + j];
            #pragma unroll
            for (int dd = 0; dd < 32; dd++)
                oacc[dd] += p * kt[j*QS_STRIDE + d0 + dd];
        }
    }
    float* orow = attn + ((size_t)(rb + qt*QT + qi))*DD + h*HD + d0;
    #pragma unroll
    for (int dd = 0; dd < 32; dd++) orow[dd] = oacc[dd];
}

// ---------------- 8. mean V ----------------
__global__ void meanv_kernel(const float* __restrict__ v, float* __restrict__ attn) {
    int h = blockIdx.x, b = blockIdx.y;
    int d = threadIdx.x;
    float s = 0.f;
    for (int j = 0; j < TOPK; j++)
        s += v[((size_t)(b*TOPK + j))*DD + h*HD + d];
    attn[((size_t)(RSEL + b))*DD + h*HD + d] = s * (1.f / TOPK);
}

// ---------------- 9. add x ----------------
__global__ void addx_kernel(const float* __restrict__ x, const int* __restrict__ gidx,
                            float* __restrict__ h) {
    int r = blockIdx.x;
    int b = r / TOPK;
    int pos = gidx[r];
    const float* xr = x + ((size_t)b*SS + pos) * DD;
    float* hr = h + (size_t)r * DD;
    for (int c = threadIdx.x; c < DD; c += 256) hr[c] += xr[c];
}

// ---------------- 10. silu ----------------
__global__ void silu_mul(float* __restrict__ u1, const float* __restrict__ u3, size_t n) {
    size_t i = (size_t)blockIdx.x*256 + threadIdx.x;
    if (i < n) {
        float a = u1[i];
        float s = a / (1.f + expf(-a));
        u1[i] = s * u3[i];
    }
}

// ---------------- 11. scatter ----------------
__global__ void scatter_out(const float* __restrict__ rows, const int* __restrict__ rank,
                            float* __restrict__ dout) {
    int tok = blockIdx.x;
    int b = tok / SS;
    int rk = rank[tok];
    int srow = (rk >= 0) ? (b*TOPK + rk) : (RSEL + b);
    const float4* s4 = (const float4*)(rows + (size_t)srow * DD);
    float4* d4 = (float4*)(dout + (size_t)tok * DD);
    for (int c = threadIdx.x; c < DD/4; c += 256) d4[c] = s4[c];
}

// ---------------- launch ----------------
extern "C" void kernel_launch(void* const* d_in, const int* in_sizes, int n_in,
                              void* d_out, int out_size) {
    const float* x        = (const float*)d_in[0];
    const int*   start_p  = (const int*)  d_in[1];
    const float* freqs    = (const float*)d_in[2];
    const float* router_w = (const float*)d_in[3];
    const float* wq       = (const float*)d_in[4];
    const float* wk       = (const float*)d_in[5];
    const float* wv       = (const float*)d_in[6];
    const float* wo       = (const float*)d_in[7];
    const float* w1       = (const float*)d_in[8];
    const float* w2       = (const float*)d_in[9];
    const float* w3       = (const float*)d_in[10];
    const float* attn_nw  = (const float*)d_in[11];
    const float* ffn_nw   = (const float*)d_in[12];
    float* out = (float*)d_out;

    size_t off_tw  = (size_t)BB*SS*DD;
    size_t off_idx = off_tw + (size_t)BB*SS;
    size_t osz = (size_t)out_size;

    float *tw, *xn, *q, *k, *v, *attn, *h, *hn, *u1, *u3, *outrows;
    int *idx, *rank;
    int8_t *qa1, *qa0, *qkv1, *qkv0, *qo1, *qo0, *q13_1, *q13_0, *q2_1, *q2_0;
    float *da, *dqkv, *do_, *d13, *d2;
    cudaGetSymbolAddress((void**)&tw,   g_tw);
    cudaGetSymbolAddress((void**)&idx,  g_idx);
    cudaGetSymbolAddress((void**)&rank, g_rank);
    cudaGetSymbolAddress((void**)&xn,   g_xn);
    cudaGetSymbolAddress((void**)&q,    g_q);
    cudaGetSymbolAddress((void**)&k,    g_k);
    cudaGetSymbolAddress((void**)&v,    g_v);
    cudaGetSymbolAddress((void**)&attn, g_attn);
    cudaGetSymbolAddress((void**)&h,    g_h);
    cudaGetSymbolAddress((void**)&hn,   g_hn);
    cudaGetSymbolAddress((void**)&u1,   g_u1);
    cudaGetSymbolAddress((void**)&u3,   g_u3);
    cudaGetSymbolAddress((void**)&outrows, g_outrows);
    cudaGetSymbolAddress((void**)&qa1,  g_qa1);
    cudaGetSymbolAddress((void**)&qa0,  g_qa0);
    cudaGetSymbolAddress((void**)&da,   g_da);
    cudaGetSymbolAddress((void**)&qkv1, g_qkv1);
    cudaGetSymbolAddress((void**)&qkv0, g_qkv0);
    cudaGetSymbolAddress((void**)&dqkv, g_dqkv);
    cudaGetSymbolAddress((void**)&qo1,  g_qo1);
    cudaGetSymbolAddress((void**)&qo0,  g_qo0);
    cudaGetSymbolAddress((void**)&do_,  g_do);
    cudaGetSymbolAddress((void**)&q13_1, g_q13_1);
    cudaGetSymbolAddress((void**)&q13_0, g_q13_0);
    cudaGetSymbolAddress((void**)&d13,  g_d13);
    cudaGetSymbolAddress((void**)&q2_1, g_q2_1);
    cudaGetSymbolAddress((void**)&q2_0, g_q2_0);
    cudaGetSymbolAddress((void**)&d2,   g_d2);

    int attn_smem = (QT*QS_STRIDE + KC*QS_STRIDE + QT*SC_STRIDE) * 4;
    cudaFuncSetAttribute(attn_kernel, cudaFuncAttributeMaxDynamicSharedMemorySize, attn_smem);
    cudaFuncSetAttribute(i8_gemm, cudaFuncAttributeMaxDynamicSharedMemorySize, I8_SMEM);

    const int MTILES_SEL = RSEL / IBM;              // 4
    const int MTILES_TOT = (RTOT + IBM - 1) / IBM;  // 5

    // ---- weight quantization (independent of activations) ----
    colmax_kernel<<<DD/64, 256>>>(wq, dqkv + 0*DD, DD, DD);
    colmax_kernel<<<DD/64, 256>>>(wk, dqkv + 1*DD, DD, DD);
    colmax_kernel<<<DD/64, 256>>>(wv, dqkv + 2*DD, DD, DD);
    colmax_kernel<<<DD/64, 256>>>(wo, do_, DD, DD);
    colmax_kernel<<<HIDDEN/64, 256>>>(w1, d13 + 0, DD, HIDDEN);
    colmax_kernel<<<HIDDEN/64, 256>>>(w3, d13 + HIDDEN, DD, HIDDEN);
    colmax_kernel<<<DD/64, 256>>>(w2, d2, HIDDEN, DD);
    quantB_kernel<<<dim3(DD/64, DD/64), 256>>>(wq, dqkv + 0*DD, qkv1 + 0*(size_t)DD*DD, qkv0 + 0*(size_t)DD*DD, DD, DD);
    quantB_kernel<<<dim3(DD/64, DD/64), 256>>>(wk, dqkv + 1*DD, qkv1 + 1*(size_t)DD*DD, qkv0 + 1*(size_t)DD*DD, DD, DD);
    quantB_kernel<<<dim3(DD/64, DD/64), 256>>>(wv, dqkv + 2*DD, qkv1 + 2*(size_t)DD*DD, qkv0 + 2*(size_t)DD*DD, DD, DD);
    quantB_kernel<<<dim3(DD/64, DD/64), 256>>>(wo, do_, qo1, qo0, DD, DD);
    quantB_kernel<<<dim3(HIDDEN/64, DD/64), 256>>>(w1, d13 + 0, q13_1 + 0, q13_0 + 0, DD, HIDDEN);
    quantB_kernel<<<dim3(HIDDEN/64, DD/64), 256>>>(w3, d13 + HIDDEN, q13_1 + (size_t)DD*HIDDEN, q13_0 + (size_t)DD*HIDDEN, DD, HIDDEN);
    quantB_kernel<<<dim3(DD/64, HIDDEN/64), 256>>>(w2, d2, q2_1, q2_0, HIDDEN, DD);

    // 1. router
    router_kernel<<<BB*SS, 256>>>(x, router_w, tw, out, off_tw, osz);
    // 2. top-k
    topk_kernel<<<BB, 1024>>>(tw, idx, out, off_idx, osz);
    // 3. rank map
    rank_init<<<(BB*SS + 255)/256, 256>>>(rank);
    rank_set<<<(RSEL + 255)/256, 256>>>(idx, rank);
    // 4. gather + rmsnorm(attn)
    rmsnorm_gather<<<RSEL, 256>>>(x, idx, attn_nw, xn);
    // 5. QKV projections (int8 split)
    quantA_kernel<<<RSEL, 256>>>(xn, qa1, qa0, da, DD);
    i8_gemm<<<dim3(DD/IBN, MTILES_SEL, 3), 256, I8_SMEM>>>(
        qa1, qa0, da, qkv1, qkv0, dqkv, q, k, v, RSEL, DD, DD);
    // 6. rotary
    rotary_kernel<<<RSEL, 256>>>(q, k, idx, freqs, start_p);
    // 7. attention
    attn_kernel<<<dim3(TOPK/QT, HH, BB), 256, attn_smem>>>(q, k, v, attn);
    // 8. shared row = mean V
    meanv_kernel<<<dim3(HH, BB), HD>>>(v, attn);
    // 9. wo projection + add x
    quantA_kernel<<<RTOT, 256>>>(attn, qa1, qa0, da, DD);
    i8_gemm<<<dim3(DD/IBN, MTILES_TOT, 1), 256, I8_SMEM>>>(
        qa1, qa0, da, qo1, qo0, do_, h, h, h, RTOT, DD, DD);
    addx_kernel<<<RSEL, 256>>>(x, idx, h);
    // 10. ffn rmsnorm
    rmsnorm_rows<<<RTOT, 256>>>(h, ffn_nw, hn);
    // 11. FFN
    quantA_kernel<<<RTOT, 256>>>(hn, qa1, qa0, da, DD);
    i8_gemm<<<dim3(HIDDEN/IBN, MTILES_TOT, 2), 256, I8_SMEM>>>(
        qa1, qa0, da, q13_1, q13_0, d13, u1, u3, u3, RTOT, DD, HIDDEN);
    {
        size_t n = (size_t)RTOT * HIDDEN;
        silu_mul<<<(unsigned)((n + 255)/256), 256>>>(u1, u3, n);
    }
    quantA_kernel<<<RTOT, 256>>>(u1, qa1, qa0, da, HIDDEN);
    i8_gemm<<<dim3(DD/IBN, MTILES_TOT, 1), 256, I8_SMEM>>>(
        qa1, qa0, da, q2_1, q2_0, d2, outrows, outrows, outrows, RTOT, HIDDEN, DD);
    // 12. scatter
    scatter_out<<<BB*SS, 256>>>(outrows, rank, out);
}

// round 12
// speedup vs baseline: 2.4198x; 2.4198x over previous
#include <cuda_runtime.h>
#include <cuda_bf16.h>
#include <cuda_fp16.h>
#include <math.h>
#include <cstdint>

// Problem constants
#define BB 2
#define SS 2048
#define DD 2048
#define HH 16
#define HD 128
#define TOPK 256
#define HIDDEN 8192
#define RSEL (BB*TOPK)      // 512 selected rows total
#define RTOT (RSEL + BB)    // + 1 shared row per batch = 514
#define EPS 1e-6f

// ---------------- scratch (static device globals; no allocs allowed) ----------------
__device__ float g_tw[BB*SS];
__device__ int   g_idx[BB*TOPK];
__device__ int   g_rank[BB*SS];
__device__ float g_xn[RSEL*DD];
__device__ float g_q[RSEL*DD];
__device__ float g_k[RSEL*DD];
__device__ float g_v[RSEL*DD];
__device__ float g_attn[RTOT*DD];
__device__ float g_h[RTOT*DD];
__device__ float g_hn[RTOT*DD];
__device__ float g_u1[RTOT*HIDDEN];
__device__ float g_u3[RTOT*HIDDEN];
__device__ float g_outrows[RTOT*DD];
// fp16 hi/lo pre-split buffers
__device__ __half g_ah[RTOT*HIDDEN];
__device__ __half g_al[RTOT*HIDDEN];
__device__ __half g_whqkv[3u*DD*DD];
__device__ __half g_wlqkv[3u*DD*DD];
__device__ __half g_who[DD*DD];
__device__ __half g_wlo[DD*DD];
__device__ __half g_wh13[2u*DD*HIDDEN];
__device__ __half g_wl13[2u*DD*HIDDEN];
__device__ __half g_whw2[(size_t)DD*HIDDEN];
__device__ __half g_wlw2[(size_t)DD*HIDDEN];
__device__ float  g_part[4u*RTOT*DD];

// ================= helpers =================
__device__ __forceinline__ uint32_t smem_u32(const void* p) {
    uint32_t a;
    asm("{ .reg .u64 t; cvta.to.shared.u64 t, %1; cvt.u32.u64 %0, t; }" : "=r"(a) : "l"(p));
    return a;
}
__device__ __forceinline__ void cpa16(uint32_t dst, const void* src, int sz) {
    asm volatile("cp.async.cg.shared.global [%0], [%1], 16, %2;" :: "r"(dst), "l"(src), "r"(sz) : "memory");
}
#define CP_COMMIT() asm volatile("cp.async.commit_group;" ::: "memory")

__device__ __forceinline__ void mma_f16(float* cc, const uint32_t* a, const uint32_t* b) {
    asm volatile(
        "mma.sync.aligned.m16n8k16.row.col.f32.f16.f16.f32 "
        "{%0,%1,%2,%3},{%4,%5,%6,%7},{%8,%9},{%0,%1,%2,%3};"
        : "+f"(cc[0]), "+f"(cc[1]), "+f"(cc[2]), "+f"(cc[3])
        : "r"(a[0]), "r"(a[1]), "r"(a[2]), "r"(a[3]), "r"(b[0]), "r"(b[1]));
}
__device__ __forceinline__ void hsplit(float f, __half& h, __half& l) {
    h = __float2half_rn(f);
    l = __float2half_rn(f - __half2float(h));
}

// ================= conversion kernels =================
// A[M][K] fp32 -> Ah, Al [M][K] half
__global__ void convA_kernel(const float* __restrict__ A, __half* __restrict__ Ah,
                             __half* __restrict__ Al, int K) {
    int row = blockIdx.x;
    const float* ar = A + (size_t)row * K;
    for (int base = threadIdx.x * 8; base < K; base += 2048) {
        float4 v0 = *(const float4*)(ar + base);
        float4 v1 = *(const float4*)(ar + base + 4);
        __half h[8], l[8];
        const float* vp0 = &v0.x; const float* vp1 = &v1.x;
        #pragma unroll
        for (int j = 0; j < 4; j++) { hsplit(vp0[j], h[j], l[j]); hsplit(vp1[j], h[4+j], l[4+j]); }
        uint32_t wh[4], wl[4];
        #pragma unroll
        for (int w = 0; w < 4; w++) {
            __half2 hh = __halves2half2(h[2*w], h[2*w+1]);
            __half2 ll = __halves2half2(l[2*w], l[2*w+1]);
            wh[w] = *reinterpret_cast<uint32_t*>(&hh);
            wl[w] = *reinterpret_cast<uint32_t*>(&ll);
        }
        *(uint4*)(Ah + (size_t)row * K + base) = make_uint4(wh[0], wh[1], wh[2], wh[3]);
        *(uint4*)(Al + (size_t)row * K + base) = make_uint4(wl[0], wl[1], wl[2], wl[3]);
    }
}

// W[K][N] fp32 -> Wh, Wl [N][K] half (transposed)
__global__ void convW_kernel(const float* __restrict__ W, __half* __restrict__ Wh,
                             __half* __restrict__ Wl, int K, int N) {
    __shared__ float ts[64][65];
    int t = threadIdx.x;
    int n0 = blockIdx.x * 64, k0 = blockIdx.y * 64;
    #pragma unroll
    for (int i = 0; i < 16; i++) {
        int idx = t + 256 * i;
        int kk = idx >> 6, nn = idx & 63;
        ts[kk][nn] = W[(size_t)(k0 + kk) * N + n0 + nn];
    }
    __syncthreads();
    int j = t >> 2, ch = t & 3;            // j = local n, ch selects 16 k's
    int n = n0 + j;
    uint32_t wh[8], wl[8];
    #pragma unroll
    for (int w = 0; w < 8; w++) {
        __half h0, l0, h1, l1;
        hsplit(ts[ch * 16 + 2*w][j], h0, l0);
        hsplit(ts[ch * 16 + 2*w + 1][j], h1, l1);
        __half2 hh = __halves2half2(h0, h1);
        __half2 ll = __halves2half2(l0, l1);
        wh[w] = *reinterpret_cast<uint32_t*>(&hh);
        wl[w] = *reinterpret_cast<uint32_t*>(&ll);
    }
    size_t o = (size_t)n * K + k0 + ch * 16;
    *(uint4*)(Wh + o)     = make_uint4(wh[0], wh[1], wh[2], wh[3]);
    *(uint4*)(Wh + o + 8) = make_uint4(wh[4], wh[5], wh[6], wh[7]);
    *(uint4*)(Wl + o)     = make_uint4(wl[0], wl[1], wl[2], wl[3]);
    *(uint4*)(Wl + o + 8) = make_uint4(wl[4], wl[5], wl[6], wl[7]);
}

// ================= fp16x3 GEMM, pre-split operands =================
// C[M,N] = A[M,K] @ B[K,N]; A as [M][K] hi/lo half, B as [N][K] hi/lo half.
#define BM 128
#define BN 128
#define BKK 32
#define HPART 16384                      // bytes per part (128 rows x 128B swizzled)
#define HSTAGE (4*HPART)                 // Ahi, Alo, Bhi, Blo
#define GEMM_SMEM (2*HSTAGE)             // 131072

__device__ __forceinline__ uint32_t hswz(int row, int u, int c4) {
    return (uint32_t)(row * 128 + ((u ^ (row & 7)) << 4) + c4);
}

__device__ __forceinline__ void h_load_stage(
    const __half* __restrict__ Ah, const __half* __restrict__ Al,
    const __half* __restrict__ Bh, const __half* __restrict__ Bl,
    uint32_t sbase, int buf, int bm, int bn, int k0, int M, int K, int tid)
{
    uint32_t st = sbase + (uint32_t)buf * HSTAGE;
    #pragma unroll
    for (int i = 0; i < 2; i++) {
        int g = tid + 256 * i;           // 0..511
        int row = g >> 2, u = g & 3;
        uint32_t doff = (uint32_t)(row * 128 + ((u ^ (row & 7)) << 4));
        // A (rows bm+row)
        int gm = bm + row;
        int sz = (gm < M) ? 16 : 0;
        int gmc = (gm < M) ? gm : (M - 1);
        size_t ga = (size_t)gmc * K + k0 + u * 8;
        cpa16(st + doff,           Ah + ga, sz);
        cpa16(st + HPART + doff,   Al + ga, sz);
        // B (n = bn+row)
        size_t gb = (size_t)(bn + row) * K + k0 + u * 8;
        cpa16(st + 2*HPART + doff, Bh + gb, 16);
        cpa16(st + 3*HPART + doff, Bl + gb, 16);
    }
    CP_COMMIT();
}

__global__ void __launch_bounds__(256) hgemm(
    const __half* __restrict__ Ah, const __half* __restrict__ Al,
    const __half* __restrict__ Bh, const __half* __restrict__ Bl,
    float* C0c, float* C1c, float* C2c, float* C3c,
    int M, int K, int N, int kmode)
{
    extern __shared__ char sm8[];
    int z = blockIdx.z;
    const __half *Bh_, *Bl_;
    float* C;
    int kbase, Keff;
    if (kmode == 0) {
        Bh_ = Bh + (size_t)z * N * K;
        Bl_ = Bl + (size_t)z * N * K;
        C = (z == 0) ? C0c : ((z == 1) ? C1c : C2c);
        kbase = 0; Keff = K;
    } else {
        Bh_ = Bh; Bl_ = Bl;
        C = (z == 0) ? C0c : ((z == 1) ? C1c : ((z == 2) ? C2c : C3c));
        Keff = K >> 2; kbase = z * Keff;
    }
    uint32_t sbase = smem_u32(sm8);
    int tid = threadIdx.x;
    int bm = blockIdx.y * BM, bn = blockIdx.x * BN;
    int lane = tid & 31, wid = tid >> 5;
    int r = lane >> 2, c = lane & 3;
    int c4 = c * 4;
    int m_base = (wid >> 2) * 64;
    int n_base = (wid & 3) * 32;

    float acc[4][4][4];
    #pragma unroll
    for (int mt = 0; mt < 4; mt++)
        #pragma unroll
        for (int nt = 0; nt < 4; nt++)
            #pragma unroll
            for (int q = 0; q < 4; q++) acc[mt][nt][q] = 0.f;

    int T = Keff / BKK;
    h_load_stage(Ah, Al, Bh_, Bl_, sbase, 0, bm, bn, kbase, M, K, tid);

    for (int i = 0; i < T; i++) {
        int buf = i & 1;
        if (i + 1 < T) {
            h_load_stage(Ah, Al, Bh_, Bl_, sbase, buf ^ 1, bm, bn, kbase + (i + 1) * BKK, M, K, tid);
            asm volatile("cp.async.wait_group 1;" ::: "memory");
        } else {
            asm volatile("cp.async.wait_group 0;" ::: "memory");
        }
        __syncthreads();

        const char* sAh = sm8 + buf * HSTAGE;
        const char* sAl = sAh + HPART;
        const char* sBh = sAh + 2*HPART;
        const char* sBl = sAh + 3*HPART;
        #pragma unroll
        for (int ks = 0; ks < 2; ks++) {
            int u0 = 2 * ks, u1 = 2 * ks + 1;
            uint32_t ah[4][4], al[4][4];
            #pragma unroll
            for (int mt = 0; mt < 4; mt++) {
                int row0 = m_base + mt * 16 + r;
                ah[mt][0] = *(const uint32_t*)(sAh + hswz(row0,     u0, c4));
                ah[mt][1] = *(const uint32_t*)(sAh + hswz(row0 + 8, u0, c4));
                ah[mt][2] = *(const uint32_t*)(sAh + hswz(row0,     u1, c4));
                ah[mt][3] = *(const uint32_t*)(sAh + hswz(row0 + 8, u1, c4));
                al[mt][0] = *(const uint32_t*)(sAl + hswz(row0,     u0, c4));
                al[mt][1] = *(const uint32_t*)(sAl + hswz(row0 + 8, u0, c4));
                al[mt][2] = *(const uint32_t*)(sAl + hswz(row0,     u1, c4));
                al[mt][3] = *(const uint32_t*)(sAl + hswz(row0 + 8, u1, c4));
            }
            uint32_t bh[4][2], bl[4][2];
            #pragma unroll
            for (int nt = 0; nt < 4; nt++) {
                int n = n_base + nt * 8 + r;
                bh[nt][0] = *(const uint32_t*)(sBh + hswz(n, u0, c4));
                bh[nt][1] = *(const uint32_t*)(sBh + hswz(n, u1, c4));
                bl[nt][0] = *(const uint32_t*)(sBl + hswz(n, u0, c4));
                bl[nt][1] = *(const uint32_t*)(sBl + hswz(n, u1, c4));
            }
            #pragma unroll
            for (int mt = 0; mt < 4; mt++)
                #pragma unroll
                for (int nt = 0; nt < 4; nt++) {
                    mma_f16(acc[mt][nt], al[mt], bh[nt]);
                    mma_f16(acc[mt][nt], ah[mt], bl[nt]);
                    mma_f16(acc[mt][nt], ah[mt], bh[nt]);
                }
        }
        __syncthreads();
    }

    #pragma unroll
    for (int mt = 0; mt < 4; mt++) {
        int row0 = bm + m_base + mt * 16 + r;
        #pragma unroll
        for (int nt = 0; nt < 4; nt++) {
            int col = bn + n_base + nt * 8 + c * 2;
            if (row0 < M) {
                float2 v = make_float2(acc[mt][nt][0], acc[mt][nt][1]);
                *(float2*)(C + (size_t)row0 * N + col) = v;
            }
            if (row0 + 8 < M) {
                float2 v = make_float2(acc[mt][nt][2], acc[mt][nt][3]);
                *(float2*)(C + (size_t)(row0 + 8) * N + col) = v;
            }
        }
    }
}

// sum 4 split-K partials
__global__ void reduce4_kernel(const float* __restrict__ p, float* __restrict__ out) {
    size_t i = ((size_t)blockIdx.x * 256 + threadIdx.x) * 4;
    size_t n = (size_t)RTOT * DD;
    if (i < n) {
        float4 a = *(const float4*)(p + i);
        float4 b = *(const float4*)(p + n + i);
        float4 cc = *(const float4*)(p + 2*n + i);
        float4 d = *(const float4*)(p + 3*n + i);
        float4 o = make_float4(a.x+b.x+cc.x+d.x, a.y+b.y+cc.y+d.y,
                               a.z+b.z+cc.z+d.z, a.w+b.w+cc.w+d.w);
        *(float4*)(out + i) = o;
    }
}

// ---------------- 1. router ----------------
__global__ void router_kernel(const float* __restrict__ x, const float* __restrict__ rw,
                              float* __restrict__ tw, float* __restrict__ dout,
                              size_t off_tw, size_t out_size) {
    int tok = blockIdx.x;
    __shared__ float red[256];
    float s = 0.f;
    const float* xr = x + (size_t)tok * DD;
    for (int c = threadIdx.x; c < DD; c += 256) s += xr[c] * rw[c];
    red[threadIdx.x] = s; __syncthreads();
    for (int o = 128; o > 0; o >>= 1) {
        if (threadIdx.x < o) red[threadIdx.x] += red[threadIdx.x + o];
        __syncthreads();
    }
    if (threadIdx.x == 0) {
        tw[tok] = red[0];
        if (off_tw + (size_t)tok < out_size) dout[off_tw + tok] = red[0];
    }
}

// ---------------- 2. top-k ----------------
__global__ void topk_kernel(const float* __restrict__ tw, int* __restrict__ gidx,
                            float* __restrict__ dout, size_t off_idx, size_t out_size) {
    __shared__ float v[SS];
    __shared__ int   id[SS];
    int b = blockIdx.x;
    int t = threadIdx.x;
    for (int i = t; i < SS; i += 1024) { v[i] = tw[b*SS + i]; id[i] = i; }
    __syncthreads();
    for (int k = 2; k <= SS; k <<= 1) {
        for (int j = k >> 1; j > 0; j >>= 1) {
            for (int i = t; i < SS; i += 1024) {
                int ixj = i ^ j;
                if (ixj > i) {
                    bool up = ((i & k) == 0);
                    float va = v[i], vb = v[ixj];
                    int   ia = id[i], ib = id[ixj];
                    bool aBeforeB = (va > vb) || (va == vb && ia < ib);
                    bool sw = up ? !aBeforeB : aBeforeB;
                    if (sw) { v[i]=vb; v[ixj]=va; id[i]=ib; id[ixj]=ia; }
                }
            }
            __syncthreads();
        }
    }
    for (int i = t; i < TOPK; i += 1024) {
        gidx[b*TOPK + i] = id[i];
        size_t o = off_idx + (size_t)b*TOPK + i;
        if (o < out_size) dout[o] = (float)id[i];
    }
}

// ---------------- 3. rank map ----------------
__global__ void rank_init(int* __restrict__ rank) {
    int i = blockIdx.x*256 + threadIdx.x;
    if (i < BB*SS) rank[i] = -1;
}
__global__ void rank_set(const int* __restrict__ gidx, int* __restrict__ rank) {
    int r = blockIdx.x*256 + threadIdx.x;
    if (r < RSEL) {
        int b = r / TOPK;
        rank[b*SS + gidx[r]] = r % TOPK;
    }
}

// ---------------- 4. gather + rmsnorm ----------------
__global__ void rmsnorm_gather(const float* __restrict__ x, const int* __restrict__ gidx,
                               const float* __restrict__ w, float* __restrict__ out) {
    int r = blockIdx.x;
    int b = r / TOPK;
    int pos = gidx[r];
    const float* xr = x + ((size_t)b*SS + pos) * DD;
    __shared__ float red[256];
    float s = 0.f;
    for (int c = threadIdx.x; c < DD; c += 256) { float v = xr[c]; s += v*v; }
    red[threadIdx.x] = s; __syncthreads();
    for (int o = 128; o > 0; o >>= 1) {
        if (threadIdx.x < o) red[threadIdx.x] += red[threadIdx.x + o];
        __syncthreads();
    }
    float rms = rsqrtf(red[0] / (float)DD + EPS);
    float* orow = out + (size_t)r * DD;
    for (int c = threadIdx.x; c < DD; c += 256) orow[c] = xr[c] * rms * w[c];
}

__global__ void rmsnorm_rows(const float* __restrict__ in, const float* __restrict__ w,
                             float* __restrict__ out) {
    int r = blockIdx.x;
    const float* xr = in + (size_t)r * DD;
    __shared__ float red[256];
    float s = 0.f;
    for (int c = threadIdx.x; c < DD; c += 256) { float v = xr[c]; s += v*v; }
    red[threadIdx.x] = s; __syncthreads();
    for (int o = 128; o > 0; o >>= 1) {
        if (threadIdx.x < o) red[threadIdx.x] += red[threadIdx.x + o];
        __syncthreads();
    }
    float rms = rsqrtf(red[0] / (float)DD + EPS);
    float* orow = out + (size_t)r * DD;
    for (int c = threadIdx.x; c < DD; c += 256) orow[c] = xr[c] * rms * w[c];
}

// ---------------- 6. rotary ----------------
__global__ void rotary_kernel(float* __restrict__ q, float* __restrict__ k,
                              const int* __restrict__ gidx, const float* __restrict__ freqs,
                              const int* __restrict__ startp) {
    int r = blockIdx.x;
    int pos = startp[0] + gidx[r];
    const float* f = freqs + (size_t)pos * HD;
    size_t base = (size_t)r * DD;
    for (int e = threadIdx.x; e < HH*HD/2; e += 256) {
        int hp = e & 63;
        float c = f[hp*2], sn = f[hp*2+1];
        size_t i0 = base + (size_t)e*2;
        float q0 = q[i0], q1 = q[i0+1];
        q[i0]   = q0*c - q1*sn;
        q[i0+1] = q0*sn + q1*c;
        float k0 = k[i0], k1 = k[i0+1];
        k[i0]   = k0*c - k1*sn;
        k[i0+1] = k0*sn + k1*c;
    }
}

// ---------------- 7. attention ----------------
#define QT 64
#define KC 64
#define QS_STRIDE 129
#define SC_STRIDE 257
__global__ void attn_kernel(const float* __restrict__ q, const float* __restrict__ k,
                            const float* __restrict__ v, float* __restrict__ attn) {
    extern __shared__ float smf[];
    float* qs = smf;
    float* kt = qs + QT*QS_STRIDE;
    float* sc = kt + KC*QS_STRIDE;
    int qt = blockIdx.x, h = blockIdx.y, b = blockIdx.z;
    int t = threadIdx.x;
    int rb = b * TOPK;
    for (int l = t; l < QT*HD; l += 256) {
        int qi = l / HD, d = l % HD;
        qs[qi*QS_STRIDE + d] = q[((size_t)(rb + qt*QT + qi))*DD + h*HD + d];
    }
    const float scale = 0.08838834764831845f;
    int qi = t >> 2;
    {
        int kj0 = (t & 3) * 16;
        for (int kc = 0; kc < TOPK/KC; kc++) {
            __syncthreads();
            for (int l = t; l < KC*HD; l += 256) {
                int kj = l / HD, d = l % HD;
                kt[kj*QS_STRIDE + d] = k[((size_t)(rb + kc*KC + kj))*DD + h*HD + d];
            }
            __syncthreads();
            float acc[16];
            #pragma unroll
            for (int n = 0; n < 16; n++) acc[n] = 0.f;
            for (int d = 0; d < HD; d++) {
                float qv = qs[qi*QS_STRIDE + d];
                #pragma unroll
                for (int n = 0; n < 16; n++)
                    acc[n] += qv * kt[(kj0+n)*QS_STRIDE + d];
            }
            #pragma unroll
            for (int n = 0; n < 16; n++)
                sc[qi*SC_STRIDE + kc*KC + kj0 + n] = acc[n] * scale;
        }
    }
    __syncthreads();
    if (t < QT) {
        float m = -1e30f;
        for (int j = 0; j < TOPK; j++) m = fmaxf(m, sc[t*SC_STRIDE + j]);
        float s = 0.f;
        for (int j = 0; j < TOPK; j++) {
            float e = expf(sc[t*SC_STRIDE + j] - m);
            sc[t*SC_STRIDE + j] = e; s += e;
        }
        float inv = 1.f / s;
        for (int j = 0; j < TOPK; j++) sc[t*SC_STRIDE + j] *= inv;
    }
    __syncthreads();
    int d0 = (t & 3) * 32;
    float oacc[32];
    #pragma unroll
    for (int i = 0; i < 32; i++) oacc[i] = 0.f;
    for (int kc = 0; kc < TOPK/KC; kc++) {
        __syncthreads();
        for (int l = t; l < KC*HD; l += 256) {
            int kj = l / HD, d = l % HD;
            kt[kj*QS_STRIDE + d] = v[((size_t)(rb + kc*KC + kj))*DD + h*HD + d];
        }
        __syncthreads();
        for (int j = 0; j < KC; j++) {
            float p = sc[qi*SC_STRIDE + kc*KC + j];
            #pragma unroll
            for (int dd = 0; dd < 32; dd++)
                oacc[dd] += p * kt[j*QS_STRIDE + d0 + dd];
        }
    }
    float* orow = attn + ((size_t)(rb + qt*QT + qi))*DD + h*HD + d0;
    #pragma unroll
    for (int dd = 0; dd < 32; dd++) orow[dd] = oacc[dd];
}

// ---------------- 8. mean V ----------------
__global__ void meanv_kernel(const float* __restrict__ v, float* __restrict__ attn) {
    int h = blockIdx.x, b = blockIdx.y;
    int d = threadIdx.x;
    float s = 0.f;
    for (int j = 0; j < TOPK; j++)
        s += v[((size_t)(b*TOPK + j))*DD + h*HD + d];
    attn[((size_t)(RSEL + b))*DD + h*HD + d] = s * (1.f / TOPK);
}

// ---------------- 9. add x ----------------
__global__ void addx_kernel(const float* __restrict__ x, const int* __restrict__ gidx,
                            float* __restrict__ h) {
    int r = blockIdx.x;
    int b = r / TOPK;
    int pos = gidx[r];
    const float* xr = x + ((size_t)b*SS + pos) * DD;
    float* hr = h + (size_t)r * DD;
    for (int c = threadIdx.x; c < DD; c += 256) hr[c] += xr[c];
}

// ---------------- 10. silu ----------------
__global__ void silu_mul(float* __restrict__ u1, const float* __restrict__ u3, size_t n) {
    size_t i = (size_t)blockIdx.x*256 + threadIdx.x;
    if (i < n) {
        float a = u1[i];
        float s = a / (1.f + expf(-a));
        u1[i] = s * u3[i];
    }
}

// ---------------- 11. scatter ----------------
__global__ void scatter_out(const float* __restrict__ rows, const int* __restrict__ rank,
                            float* __restrict__ dout) {
    int tok = blockIdx.x;
    int b = tok / SS;
    int rk = rank[tok];
    int srow = (rk >= 0) ? (b*TOPK + rk) : (RSEL + b);
    const float4* s4 = (const float4*)(rows + (size_t)srow * DD);
    float4* d4 = (float4*)(dout + (size_t)tok * DD);
    for (int c = threadIdx.x; c < DD/4; c += 256) d4[c] = s4[c];
}

// ---------------- launch ----------------
extern "C" void kernel_launch(void* const* d_in, const int* in_sizes, int n_in,
                              void* d_out, int out_size) {
    const float* x        = (const float*)d_in[0];
    const int*   start_p  = (const int*)  d_in[1];
    const float* freqs    = (const float*)d_in[2];
    const float* router_w = (const float*)d_in[3];
    const float* wq       = (const float*)d_in[4];
    const float* wk       = (const float*)d_in[5];
    const float* wv       = (const float*)d_in[6];
    const float* wo       = (const float*)d_in[7];
    const float* w1       = (const float*)d_in[8];
    const float* w2       = (const float*)d_in[9];
    const float* w3       = (const float*)d_in[10];
    const float* attn_nw  = (const float*)d_in[11];
    const float* ffn_nw   = (const float*)d_in[12];
    float* out = (float*)d_out;

    size_t off_tw  = (size_t)BB*SS*DD;
    size_t off_idx = off_tw + (size_t)BB*SS;
    size_t osz = (size_t)out_size;

    float *tw, *xn, *q, *k, *v, *attn, *h, *hn, *u1, *u3, *outrows, *part;
    int *idx, *rank;
    __half *ah, *al, *whqkv, *wlqkv, *who, *wlo_, *wh13, *wl13, *whw2, *wlw2;
    cudaGetSymbolAddress((void**)&tw,   g_tw);
    cudaGetSymbolAddress((void**)&idx,  g_idx);
    cudaGetSymbolAddress((void**)&rank, g_rank);
    cudaGetSymbolAddress((void**)&xn,   g_xn);
    cudaGetSymbolAddress((void**)&q,    g_q);
    cudaGetSymbolAddress((void**)&k,    g_k);
    cudaGetSymbolAddress((void**)&v,    g_v);
    cudaGetSymbolAddress((void**)&attn, g_attn);
    cudaGetSymbolAddress((void**)&h,    g_h);
    cudaGetSymbolAddress((void**)&hn,   g_hn);
    cudaGetSymbolAddress((void**)&u1,   g_u1);
    cudaGetSymbolAddress((void**)&u3,   g_u3);
    cudaGetSymbolAddress((void**)&outrows, g_outrows);
    cudaGetSymbolAddress((void**)&part, g_part);
    cudaGetSymbolAddress((void**)&ah,   g_ah);
    cudaGetSymbolAddress((void**)&al,   g_al);
    cudaGetSymbolAddress((void**)&whqkv, g_whqkv);
    cudaGetSymbolAddress((void**)&wlqkv, g_wlqkv);
    cudaGetSymbolAddress((void**)&who,  g_who);
    cudaGetSymbolAddress((void**)&wlo_, g_wlo);
    cudaGetSymbolAddress((void**)&wh13, g_wh13);
    cudaGetSymbolAddress((void**)&wl13, g_wl13);
    cudaGetSymbolAddress((void**)&whw2, g_whw2);
    cudaGetSymbolAddress((void**)&wlw2, g_wlw2);

    int attn_smem = (QT*QS_STRIDE + KC*QS_STRIDE + QT*SC_STRIDE) * 4;
    cudaFuncSetAttribute(attn_kernel, cudaFuncAttributeMaxDynamicSharedMemorySize, attn_smem);
    cudaFuncSetAttribute(hgemm, cudaFuncAttributeMaxDynamicSharedMemorySize, GEMM_SMEM);

    const int MTILES_SEL = RSEL / BM;              // 4
    const int MTILES_TOT = (RTOT + BM - 1) / BM;   // 5
    size_t dd2 = (size_t)DD * DD;
    size_t dh  = (size_t)DD * HIDDEN;

    // ---- weight pre-split (hi/lo fp16, transposed to [N][K]) ----
    convW_kernel<<<dim3(DD/64, DD/64), 256>>>(wq, whqkv,        wlqkv,        DD, DD);
    convW_kernel<<<dim3(DD/64, DD/64), 256>>>(wk, whqkv + dd2,  wlqkv + dd2,  DD, DD);
    convW_kernel<<<dim3(DD/64, DD/64), 256>>>(wv, whqkv + 2*dd2,wlqkv + 2*dd2,DD, DD);
    convW_kernel<<<dim3(DD/64, DD/64), 256>>>(wo, who, wlo_, DD, DD);
    convW_kernel<<<dim3(HIDDEN/64, DD/64), 256>>>(w1, wh13,      wl13,      DD, HIDDEN);
    convW_kernel<<<dim3(HIDDEN/64, DD/64), 256>>>(w3, wh13 + dh, wl13 + dh, DD, HIDDEN);
    convW_kernel<<<dim3(DD/64, HIDDEN/64), 256>>>(w2, whw2, wlw2, HIDDEN, DD);

    // 1. router (exact fp32 -> identical top-k)
    router_kernel<<<BB*SS, 256>>>(x, router_w, tw, out, off_tw, osz);
    // 2. top-k
    topk_kernel<<<BB, 1024>>>(tw, idx, out, off_idx, osz);
    // 3. rank map
    rank_init<<<(BB*SS + 255)/256, 256>>>(rank);
    rank_set<<<(RSEL + 255)/256, 256>>>(idx, rank);
    // 4. gather + rmsnorm(attn)
    rmsnorm_gather<<<RSEL, 256>>>(x, idx, attn_nw, xn);
    // 5. QKV projections
    convA_kernel<<<RSEL, 256>>>(xn, ah, al, DD);
    hgemm<<<dim3(DD/BN, MTILES_SEL, 3), 256, GEMM_SMEM>>>(
        ah, al, whqkv, wlqkv, q, k, v, nullptr, RSEL, DD, DD, 0);
    // 6. rotary
    rotary_kernel<<<RSEL, 256>>>(q, k, idx, freqs, start_p);
    // 7. attention
    attn_kernel<<<dim3(TOPK/QT, HH, BB), 256, attn_smem>>>(q, k, v, attn);
    // 8. shared row = mean V
    meanv_kernel<<<dim3(HH, BB), HD>>>(v, attn);
    // 9. wo projection + add x
    convA_kernel<<<RTOT, 256>>>(attn, ah, al, DD);
    hgemm<<<dim3(DD/BN, MTILES_TOT, 1), 256, GEMM_SMEM>>>(
        ah, al, who, wlo_, h, h, h, nullptr, RTOT, DD, DD, 0);
    addx_kernel<<<RSEL, 256>>>(x, idx, h);
    // 10. ffn rmsnorm
    rmsnorm_rows<<<RTOT, 256>>>(h, ffn_nw, hn);
    // 11. FFN
    convA_kernel<<<RTOT, 256>>>(hn, ah, al, DD);
    hgemm<<<dim3(HIDDEN/BN, MTILES_TOT, 2), 256, GEMM_SMEM>>>(
        ah, al, wh13, wl13, u1, u3, u3, nullptr, RTOT, DD, HIDDEN, 0);
    {
        size_t n = (size_t)RTOT * HIDDEN;
        silu_mul<<<(unsigned)((n + 255)/256), 256>>>(u1, u3, n);
    }
    convA_kernel<<<RTOT, 256>>>(u1, ah, al, HIDDEN);
    // w2 with split-K=4 into partial buffers, then reduce
    {
        size_t n = (size_t)RTOT * DD;
        hgemm<<<dim3(DD/BN, MTILES_TOT, 4), 256, GEMM_SMEM>>>(
            ah, al, whw2, wlw2, part, part + n, part + 2*n, part + 3*n,
            RTOT, HIDDEN, DD, 1);
        reduce4_kernel<<<(unsigned)((n/4 + 255)/256), 256>>>(part, outrows);
    }
    // 12. scatter
    scatter_out<<<BB*SS, 256>>>(outrows, rank, out);
}

// round 13
// speedup vs baseline: 2.6410x; 1.0914x over previous
#include <cuda_runtime.h>
#include <cuda_bf16.h>
#include <cuda_fp16.h>
#include <math.h>
#include <cstdint>

// Problem constants
#define BB 2
#define SS 2048
#define DD 2048
#define HH 16
#define HD 128
#define TOPK 256
#define HIDDEN 8192
#define RSEL (BB*TOPK)      // 512 selected rows total
#define RTOT (RSEL + BB)    // + 1 shared row per batch = 514
#define EPS 1e-6f

// ---------------- scratch (static device globals; no allocs allowed) ----------------
__device__ float g_tw[BB*SS];
__device__ int   g_idx[BB*TOPK];
__device__ int   g_rank[BB*SS];
__device__ float g_q[RSEL*DD];
__device__ float g_k[RSEL*DD];
__device__ float g_v[RSEL*DD];
__device__ float g_attn[RTOT*DD];
__device__ float g_h[RTOT*DD];
__device__ float g_u1[RTOT*HIDDEN];
__device__ float g_u3[RTOT*HIDDEN];
__device__ float g_outrows[RTOT*DD];
// fp16 hi/lo pre-split buffers
__device__ __half g_ah[RTOT*HIDDEN];
__device__ __half g_al[RTOT*HIDDEN];
__device__ __half g_whqkv[3u*DD*DD];
__device__ __half g_wlqkv[3u*DD*DD];
__device__ __half g_who[DD*DD];
__device__ __half g_wlo[DD*DD];
__device__ __half g_wh13[2u*DD*HIDDEN];
__device__ __half g_wl13[2u*DD*HIDDEN];
__device__ __half g_whw2[(size_t)DD*HIDDEN];
__device__ __half g_wlw2[(size_t)DD*HIDDEN];
__device__ float  g_part[4u*RTOT*HIDDEN];   // max: FFN13 2w x 2s x RTOT x HIDDEN

// ================= helpers =================
__device__ __forceinline__ uint32_t smem_u32(const void* p) {
    uint32_t a;
    asm("{ .reg .u64 t; cvta.to.shared.u64 t, %1; cvt.u32.u64 %0, t; }" : "=r"(a) : "l"(p));
    return a;
}
__device__ __forceinline__ void cpa16(uint32_t dst, const void* src, int sz) {
    asm volatile("cp.async.cg.shared.global [%0], [%1], 16, %2;" :: "r"(dst), "l"(src), "r"(sz) : "memory");
}
#define CP_COMMIT() asm volatile("cp.async.commit_group;" ::: "memory")

__device__ __forceinline__ void mma_f16(float* cc, const uint32_t* a, const uint32_t* b) {
    asm volatile(
        "mma.sync.aligned.m16n8k16.row.col.f32.f16.f16.f32 "
        "{%0,%1,%2,%3},{%4,%5,%6,%7},{%8,%9},{%0,%1,%2,%3};"
        : "+f"(cc[0]), "+f"(cc[1]), "+f"(cc[2]), "+f"(cc[3])
        : "r"(a[0]), "r"(a[1]), "r"(a[2]), "r"(a[3]), "r"(b[0]), "r"(b[1]));
}
__device__ __forceinline__ void hsplit(float f, __half& h, __half& l) {
    h = __float2half_rn(f);
    l = __float2half_rn(f - __half2float(h));
}
__device__ __forceinline__ void hsplit2_store(float r0, float r1, __half* Ah, __half* Al, size_t i) {
    __half h0, l0, h1, l1;
    hsplit(r0, h0, l0); hsplit(r1, h1, l1);
    __half2 hh = __halves2half2(h0, h1);
    __half2 ll = __halves2half2(l0, l1);
    *(__half2*)(Ah + i) = hh;
    *(__half2*)(Al + i) = ll;
}

// ================= conversion kernels =================
// A[M][K] fp32 -> Ah, Al [M][K] half
__global__ void convA_kernel(const float* __restrict__ A, __half* __restrict__ Ah,
                             __half* __restrict__ Al, int K) {
    int row = blockIdx.x;
    const float* ar = A + (size_t)row * K;
    for (int base = threadIdx.x * 8; base < K; base += 2048) {
        float4 v0 = *(const float4*)(ar + base);
        float4 v1 = *(const float4*)(ar + base + 4);
        __half h[8], l[8];
        const float* vp0 = &v0.x; const float* vp1 = &v1.x;
        #pragma unroll
        for (int j = 0; j < 4; j++) { hsplit(vp0[j], h[j], l[j]); hsplit(vp1[j], h[4+j], l[4+j]); }
        uint32_t wh[4], wl[4];
        #pragma unroll
        for (int w = 0; w < 4; w++) {
            __half2 hh = __halves2half2(h[2*w], h[2*w+1]);
            __half2 ll = __halves2half2(l[2*w], l[2*w+1]);
            wh[w] = *reinterpret_cast<uint32_t*>(&hh);
            wl[w] = *reinterpret_cast<uint32_t*>(&ll);
        }
        *(uint4*)(Ah + (size_t)row * K + base) = make_uint4(wh[0], wh[1], wh[2], wh[3]);
        *(uint4*)(Al + (size_t)row * K + base) = make_uint4(wl[0], wl[1], wl[2], wl[3]);
    }
}

// W[K][N] fp32 -> Wh, Wl [N][K] half (transposed)
__global__ void convW_kernel(const float* __restrict__ W, __half* __restrict__ Wh,
                             __half* __restrict__ Wl, int K, int N) {
    __shared__ float ts[64][65];
    int t = threadIdx.x;
    int n0 = blockIdx.x * 64, k0 = blockIdx.y * 64;
    #pragma unroll
    for (int i = 0; i < 16; i++) {
        int idx = t + 256 * i;
        int kk = idx >> 6, nn = idx & 63;
        ts[kk][nn] = W[(size_t)(k0 + kk) * N + n0 + nn];
    }
    __syncthreads();
    int j = t >> 2, ch = t & 3;
    int n = n0 + j;
    uint32_t wh[8], wl[8];
    #pragma unroll
    for (int w = 0; w < 8; w++) {
        __half h0, l0, h1, l1;
        hsplit(ts[ch * 16 + 2*w][j], h0, l0);
        hsplit(ts[ch * 16 + 2*w + 1][j], h1, l1);
        __half2 hh = __halves2half2(h0, h1);
        __half2 ll = __halves2half2(l0, l1);
        wh[w] = *reinterpret_cast<uint32_t*>(&hh);
        wl[w] = *reinterpret_cast<uint32_t*>(&ll);
    }
    size_t o = (size_t)n * K + k0 + ch * 16;
    *(uint4*)(Wh + o)     = make_uint4(wh[0], wh[1], wh[2], wh[3]);
    *(uint4*)(Wh + o + 8) = make_uint4(wh[4], wh[5], wh[6], wh[7]);
    *(uint4*)(Wl + o)     = make_uint4(wl[0], wl[1], wl[2], wl[3]);
    *(uint4*)(Wl + o + 8) = make_uint4(wl[4], wl[5], wl[6], wl[7]);
}

// ================= fp16x3 GEMM, pre-split operands, generalized split-K =================
#define BM 128
#define BN 128
#define BKK 32
#define HPART 16384
#define HSTAGE (4*HPART)
#define GEMM_SMEM (2*HSTAGE)

__device__ __forceinline__ uint32_t hswz(int row, int u, int c4) {
    return (uint32_t)(row * 128 + ((u ^ (row & 7)) << 4) + c4);
}

__device__ __forceinline__ void h_load_stage(
    const __half* __restrict__ Ah, const __half* __restrict__ Al,
    const __half* __restrict__ Bh, const __half* __restrict__ Bl,
    uint32_t sbase, int buf, int bm, int bn, int k0, int M, int K, int tid)
{
    uint32_t st = sbase + (uint32_t)buf * HSTAGE;
    #pragma unroll
    for (int i = 0; i < 2; i++) {
        int g = tid + 256 * i;
        int row = g >> 2, u = g & 3;
        uint32_t doff = (uint32_t)(row * 128 + ((u ^ (row & 7)) << 4));
        int gm = bm + row;
        int sz = (gm < M) ? 16 : 0;
        int gmc = (gm < M) ? gm : (M - 1);
        size_t ga = (size_t)gmc * K + k0 + u * 8;
        cpa16(st + doff,           Ah + ga, sz);
        cpa16(st + HPART + doff,   Al + ga, sz);
        size_t gb = (size_t)(bn + row) * K + k0 + u * 8;
        cpa16(st + 2*HPART + doff, Bh + gb, 16);
        cpa16(st + 3*HPART + doff, Bl + gb, 16);
    }
    CP_COMMIT();
}

// blockIdx.z = w*nsplit + s. Writes partial slice part[z][M][N].
__global__ void __launch_bounds__(256) hgemm(
    const __half* __restrict__ Ah, const __half* __restrict__ Al,
    const __half* __restrict__ Bh, const __half* __restrict__ Bl,
    float* __restrict__ part, int M, int K, int N, int nsplit)
{
    extern __shared__ char sm8[];
    int z = blockIdx.z;
    int w = z / nsplit, s = z % nsplit;
    const __half* Bh_ = Bh + (size_t)w * N * K;
    const __half* Bl_ = Bl + (size_t)w * N * K;
    float* C = part + (size_t)z * M * N;
    int Keff = K / nsplit;
    int kbase = s * Keff;

    uint32_t sbase = smem_u32(sm8);
    int tid = threadIdx.x;
    int bm = blockIdx.y * BM, bn = blockIdx.x * BN;
    int lane = tid & 31, wid = tid >> 5;
    int r = lane >> 2, c = lane & 3;
    int c4 = c * 4;
    int m_base = (wid >> 2) * 64;
    int n_base = (wid & 3) * 32;

    float acc[4][4][4];
    #pragma unroll
    for (int mt = 0; mt < 4; mt++)
        #pragma unroll
        for (int nt = 0; nt < 4; nt++)
            #pragma unroll
            for (int q = 0; q < 4; q++) acc[mt][nt][q] = 0.f;

    int T = Keff / BKK;
    h_load_stage(Ah, Al, Bh_, Bl_, sbase, 0, bm, bn, kbase, M, K, tid);

    for (int i = 0; i < T; i++) {
        int buf = i & 1;
        if (i + 1 < T) {
            h_load_stage(Ah, Al, Bh_, Bl_, sbase, buf ^ 1, bm, bn, kbase + (i + 1) * BKK, M, K, tid);
            asm volatile("cp.async.wait_group 1;" ::: "memory");
        } else {
            asm volatile("cp.async.wait_group 0;" ::: "memory");
        }
        __syncthreads();

        const char* sAh = sm8 + buf * HSTAGE;
        const char* sAl = sAh + HPART;
        const char* sBh = sAh + 2*HPART;
        const char* sBl = sAh + 3*HPART;
        #pragma unroll
        for (int ks = 0; ks < 2; ks++) {
            int u0 = 2 * ks, u1 = 2 * ks + 1;
            uint32_t ah[4][4], al[4][4];
            #pragma unroll
            for (int mt = 0; mt < 4; mt++) {
                int row0 = m_base + mt * 16 + r;
                ah[mt][0] = *(const uint32_t*)(sAh + hswz(row0,     u0, c4));
                ah[mt][1] = *(const uint32_t*)(sAh + hswz(row0 + 8, u0, c4));
                ah[mt][2] = *(const uint32_t*)(sAh + hswz(row0,     u1, c4));
                ah[mt][3] = *(const uint32_t*)(sAh + hswz(row0 + 8, u1, c4));
                al[mt][0] = *(const uint32_t*)(sAl + hswz(row0,     u0, c4));
                al[mt][1] = *(const uint32_t*)(sAl + hswz(row0 + 8, u0, c4));
                al[mt][2] = *(const uint32_t*)(sAl + hswz(row0,     u1, c4));
                al[mt][3] = *(const uint32_t*)(sAl + hswz(row0 + 8, u1, c4));
            }
            uint32_t bh[4][2], bl[4][2];
            #pragma unroll
            for (int nt = 0; nt < 4; nt++) {
                int n = n_base + nt * 8 + r;
                bh[nt][0] = *(const uint32_t*)(sBh + hswz(n, u0, c4));
                bh[nt][1] = *(const uint32_t*)(sBh + hswz(n, u1, c4));
                bl[nt][0] = *(const uint32_t*)(sBl + hswz(n, u0, c4));
                bl[nt][1] = *(const uint32_t*)(sBl + hswz(n, u1, c4));
            }
            #pragma unroll
            for (int mt = 0; mt < 4; mt++)
                #pragma unroll
                for (int nt = 0; nt < 4; nt++) {
                    mma_f16(acc[mt][nt], al[mt], bh[nt]);
                    mma_f16(acc[mt][nt], ah[mt], bl[nt]);
                    mma_f16(acc[mt][nt], ah[mt], bh[nt]);
                }
        }
        __syncthreads();
    }

    #pragma unroll
    for (int mt = 0; mt < 4; mt++) {
        int row0 = bm + m_base + mt * 16 + r;
        #pragma unroll
        for (int nt = 0; nt < 4; nt++) {
            int col = bn + n_base + nt * 8 + c * 2;
            if (row0 < M) {
                float2 v = make_float2(acc[mt][nt][0], acc[mt][nt][1]);
                *(float2*)(C + (size_t)row0 * N + col) = v;
            }
            if (row0 + 8 < M) {
                float2 v = make_float2(acc[mt][nt][2], acc[mt][nt][3]);
                *(float2*)(C + (size_t)(row0 + 8) * N + col) = v;
            }
        }
    }
}

// sum nsplit partial slices per weight; blockIdx.y = weight idx
__global__ void reduceN_kernel(const float* __restrict__ part,
                               float* __restrict__ d0, float* __restrict__ d1, float* __restrict__ d2,
                               int nsplit, size_t perW) {
    int w = blockIdx.y;
    float* dst = (w == 0) ? d0 : ((w == 1) ? d1 : d2);
    size_t i = ((size_t)blockIdx.x * 256 + threadIdx.x) * 4;
    if (i < perW) {
        const float* base = part + (size_t)w * nsplit * perW;
        float4 acc = *(const float4*)(base + i);
        for (int s = 1; s < nsplit; s++) {
            float4 p = *(const float4*)(base + (size_t)s * perW + i);
            acc.x += p.x; acc.y += p.y; acc.z += p.z; acc.w += p.w;
        }
        *(float4*)(dst + i) = acc;
    }
}

// ---------------- 1. router ----------------
__global__ void router_kernel(const float* __restrict__ x, const float* __restrict__ rw,
                              float* __restrict__ tw, float* __restrict__ dout,
                              size_t off_tw, size_t out_size) {
    int tok = blockIdx.x;
    __shared__ float red[256];
    float s = 0.f;
    const float* xr = x + (size_t)tok * DD;
    for (int c = threadIdx.x; c < DD; c += 256) s += xr[c] * rw[c];
    red[threadIdx.x] = s; __syncthreads();
    for (int o = 128; o > 0; o >>= 1) {
        if (threadIdx.x < o) red[threadIdx.x] += red[threadIdx.x + o];
        __syncthreads();
    }
    if (threadIdx.x == 0) {
        tw[tok] = red[0];
        if (off_tw + (size_t)tok < out_size) dout[off_tw + tok] = red[0];
    }
}

// ---------------- 2. top-k ----------------
__global__ void topk_kernel(const float* __restrict__ tw, int* __restrict__ gidx,
                            float* __restrict__ dout, size_t off_idx, size_t out_size) {
    __shared__ float v[SS];
    __shared__ int   id[SS];
    int b = blockIdx.x;
    int t = threadIdx.x;
    for (int i = t; i < SS; i += 1024) { v[i] = tw[b*SS + i]; id[i] = i; }
    __syncthreads();
    for (int k = 2; k <= SS; k <<= 1) {
        for (int j = k >> 1; j > 0; j >>= 1) {
            for (int i = t; i < SS; i += 1024) {
                int ixj = i ^ j;
                if (ixj > i) {
                    bool up = ((i & k) == 0);
                    float va = v[i], vb = v[ixj];
                    int   ia = id[i], ib = id[ixj];
                    bool aBeforeB = (va > vb) || (va == vb && ia < ib);
                    bool sw = up ? !aBeforeB : aBeforeB;
                    if (sw) { v[i]=vb; v[ixj]=va; id[i]=ib; id[ixj]=ia; }
                }
            }
            __syncthreads();
        }
    }
    for (int i = t; i < TOPK; i += 1024) {
        gidx[b*TOPK + i] = id[i];
        size_t o = off_idx + (size_t)b*TOPK + i;
        if (o < out_size) dout[o] = (float)id[i];
    }
}

// ---------------- 3. rank map ----------------
__global__ void rank_init(int* __restrict__ rank) {
    int i = blockIdx.x*256 + threadIdx.x;
    if (i < BB*SS) rank[i] = -1;
}
__global__ void rank_set(const int* __restrict__ gidx, int* __restrict__ rank) {
    int r = blockIdx.x*256 + threadIdx.x;
    if (r < RSEL) {
        int b = r / TOPK;
        rank[b*SS + gidx[r]] = r % TOPK;
    }
}

// ---------------- 4. gather + rmsnorm -> fused hi/lo split ----------------
__global__ void rmsnorm_gather_h(const float* __restrict__ x, const int* __restrict__ gidx,
                                 const float* __restrict__ w,
                                 __half* __restrict__ Ah, __half* __restrict__ Al) {
    int r = blockIdx.x;
    int b = r / TOPK;
    int pos = gidx[r];
    const float* xr = x + ((size_t)b*SS + pos) * DD;
    __shared__ float red[256];
    float s = 0.f;
    for (int c = threadIdx.x; c < DD; c += 256) { float v = xr[c]; s += v*v; }
    red[threadIdx.x] = s; __syncthreads();
    for (int o = 128; o > 0; o >>= 1) {
        if (threadIdx.x < o) red[threadIdx.x] += red[threadIdx.x + o];
        __syncthreads();
    }
    float rms = rsqrtf(red[0] / (float)DD + EPS);
    size_t base = (size_t)r * DD;
    for (int c = threadIdx.x * 2; c < DD; c += 512) {
        float r0 = xr[c] * rms * w[c];
        float r1 = xr[c+1] * rms * w[c+1];
        hsplit2_store(r0, r1, Ah, Al, base + c);
    }
}

__global__ void rmsnorm_rows_h(const float* __restrict__ in, const float* __restrict__ w,
                               __half* __restrict__ Ah, __half* __restrict__ Al) {
    int r = blockIdx.x;
    const float* xr = in + (size_t)r * DD;
    __shared__ float red[256];
    float s = 0.f;
    for (int c = threadIdx.x; c < DD; c += 256) { float v = xr[c]; s += v*v; }
    red[threadIdx.x] = s; __syncthreads();
    for (int o = 128; o > 0; o >>= 1) {
        if (threadIdx.x < o) red[threadIdx.x] += red[threadIdx.x + o];
        __syncthreads();
    }
    float rms = rsqrtf(red[0] / (float)DD + EPS);
    size_t base = (size_t)r * DD;
    for (int c = threadIdx.x * 2; c < DD; c += 512) {
        float r0 = xr[c] * rms * w[c];
        float r1 = xr[c+1] * rms * w[c+1];
        hsplit2_store(r0, r1, Ah, Al, base + c);
    }
}

// ---------------- 6. rotary ----------------
__global__ void rotary_kernel(float* __restrict__ q, float* __restrict__ k,
                              const int* __restrict__ gidx, const float* __restrict__ freqs,
                              const int* __restrict__ startp) {
    int r = blockIdx.x;
    int pos = startp[0] + gidx[r];
    const float* f = freqs + (size_t)pos * HD;
    size_t base = (size_t)r * DD;
    for (int e = threadIdx.x; e < HH*HD/2; e += 256) {
        int hp = e & 63;
        float c = f[hp*2], sn = f[hp*2+1];
        size_t i0 = base + (size_t)e*2;
        float q0 = q[i0], q1 = q[i0+1];
        q[i0]   = q0*c - q1*sn;
        q[i0+1] = q0*sn + q1*c;
        float k0 = k[i0], k1 = k[i0+1];
        k[i0]   = k0*c - k1*sn;
        k[i0+1] = k0*sn + k1*c;
    }
}

// ---------------- 7. attention ----------------
#define QT 64
#define KC 64
#define QS_STRIDE 129
#define SC_STRIDE 257
__global__ void attn_kernel(const float* __restrict__ q, const float* __restrict__ k,
                            const float* __restrict__ v, float* __restrict__ attn) {
    extern __shared__ float smf[];
    float* qs = smf;
    float* kt = qs + QT*QS_STRIDE;
    float* sc = kt + KC*QS_STRIDE;
    int qt = blockIdx.x, h = blockIdx.y, b = blockIdx.z;
    int t = threadIdx.x;
    int rb = b * TOPK;
    for (int l = t; l < QT*HD; l += 256) {
        int qi = l / HD, d = l % HD;
        qs[qi*QS_STRIDE + d] = q[((size_t)(rb + qt*QT + qi))*DD + h*HD + d];
    }
    const float scale = 0.08838834764831845f;
    int qi = t >> 2;
    {
        int kj0 = (t & 3) * 16;
        for (int kc = 0; kc < TOPK/KC; kc++) {
            __syncthreads();
            for (int l = t; l < KC*HD; l += 256) {
                int kj = l / HD, d = l % HD;
                kt[kj*QS_STRIDE + d] = k[((size_t)(rb + kc*KC + kj))*DD + h*HD + d];
            }
            __syncthreads();
            float acc[16];
            #pragma unroll
            for (int n = 0; n < 16; n++) acc[n] = 0.f;
            for (int d = 0; d < HD; d++) {
                float qv = qs[qi*QS_STRIDE + d];
                #pragma unroll
                for (int n = 0; n < 16; n++)
                    acc[n] += qv * kt[(kj0+n)*QS_STRIDE + d];
            }
            #pragma unroll
            for (int n = 0; n < 16; n++)
                sc[qi*SC_STRIDE + kc*KC + kj0 + n] = acc[n] * scale;
        }
    }
    __syncthreads();
    if (t < QT) {
        float m = -1e30f;
        for (int j = 0; j < TOPK; j++) m = fmaxf(m, sc[t*SC_STRIDE + j]);
        float s = 0.f;
        for (int j = 0; j < TOPK; j++) {
            float e = expf(sc[t*SC_STRIDE + j] - m);
            sc[t*SC_STRIDE + j] = e; s += e;
        }
        float inv = 1.f / s;
        for (int j = 0; j < TOPK; j++) sc[t*SC_STRIDE + j] *= inv;
    }
    __syncthreads();
    int d0 = (t & 3) * 32;
    float oacc[32];
    #pragma unroll
    for (int i = 0; i < 32; i++) oacc[i] = 0.f;
    for (int kc = 0; kc < TOPK/KC; kc++) {
        __syncthreads();
        for (int l = t; l < KC*HD; l += 256) {
            int kj = l / HD, d = l % HD;
            kt[kj*QS_STRIDE + d] = v[((size_t)(rb + kc*KC + kj))*DD + h*HD + d];
        }
        __syncthreads();
        for (int j = 0; j < KC; j++) {
            float p = sc[qi*SC_STRIDE + kc*KC + j];
            #pragma unroll
            for (int dd = 0; dd < 32; dd++)
                oacc[dd] += p * kt[j*QS_STRIDE + d0 + dd];
        }
    }
    float* orow = attn + ((size_t)(rb + qt*QT + qi))*DD + h*HD + d0;
    #pragma unroll
    for (int dd = 0; dd < 32; dd++) orow[dd] = oacc[dd];
}

// ---------------- 8. mean V ----------------
__global__ void meanv_kernel(const float* __restrict__ v, float* __restrict__ attn) {
    int h = blockIdx.x, b = blockIdx.y;
    int d = threadIdx.x;
    float s = 0.f;
    for (int j = 0; j < TOPK; j++)
        s += v[((size_t)(b*TOPK + j))*DD + h*HD + d];
    attn[((size_t)(RSEL + b))*DD + h*HD + d] = s * (1.f / TOPK);
}

// ---------------- 9. add x ----------------
__global__ void addx_kernel(const float* __restrict__ x, const int* __restrict__ gidx,
                            float* __restrict__ h) {
    int r = blockIdx.x;
    int b = r / TOPK;
    int pos = gidx[r];
    const float* xr = x + ((size_t)b*SS + pos) * DD;
    float* hr = h + (size_t)r * DD;
    for (int c = threadIdx.x; c < DD; c += 256) hr[c] += xr[c];
}

// ---------------- 10. silu + fused hi/lo split ----------------
__global__ void silu_mul_h(const float* __restrict__ u1, const float* __restrict__ u3,
                           __half* __restrict__ Ah, __half* __restrict__ Al, size_t n) {
    size_t i = ((size_t)blockIdx.x*256 + threadIdx.x) * 2;
    if (i < n) {
        float2 a = *(const float2*)(u1 + i);
        float2 b = *(const float2*)(u3 + i);
        float r0 = a.x / (1.f + expf(-a.x)) * b.x;
        float r1 = a.y / (1.f + expf(-a.y)) * b.y;
        hsplit2_store(r0, r1, Ah, Al, i);
    }
}

// ---------------- 11. scatter ----------------
__global__ void scatter_out(const float* __restrict__ rows, const int* __restrict__ rank,
                            float* __restrict__ dout) {
    int tok = blockIdx.x;
    int b = tok / SS;
    int rk = rank[tok];
    int srow = (rk >= 0) ? (b*TOPK + rk) : (RSEL + b);
    const float4* s4 = (const float4*)(rows + (size_t)srow * DD);
    float4* d4 = (float4*)(dout + (size_t)tok * DD);
    for (int c = threadIdx.x; c < DD/4; c += 256) d4[c] = s4[c];
}

// ---------------- launch ----------------
extern "C" void kernel_launch(void* const* d_in, const int* in_sizes, int n_in,
                              void* d_out, int out_size) {
    const float* x        = (const float*)d_in[0];
    const int*   start_p  = (const int*)  d_in[1];
    const float* freqs    = (const float*)d_in[2];
    const float* router_w = (const float*)d_in[3];
    const float* wq       = (const float*)d_in[4];
    const float* wk       = (const float*)d_in[5];
    const float* wv       = (const float*)d_in[6];
    const float* wo       = (const float*)d_in[7];
    const float* w1       = (const float*)d_in[8];
    const float* w2       = (const float*)d_in[9];
    const float* w3       = (const float*)d_in[10];
    const float* attn_nw  = (const float*)d_in[11];
    const float* ffn_nw   = (const float*)d_in[12];
    float* out = (float*)d_out;

    size_t off_tw  = (size_t)BB*SS*DD;
    size_t off_idx = off_tw + (size_t)BB*SS;
    size_t osz = (size_t)out_size;

    float *tw, *q, *k, *v, *attn, *h, *u1, *u3, *outrows, *part;
    int *idx, *rank;
    __half *ah, *al, *whqkv, *wlqkv, *who, *wlo_, *wh13, *wl13, *whw2, *wlw2;
    cudaGetSymbolAddress((void**)&tw,   g_tw);
    cudaGetSymbolAddress((void**)&idx,  g_idx);
    cudaGetSymbolAddress((void**)&rank, g_rank);
    cudaGetSymbolAddress((void**)&q,    g_q);
    cudaGetSymbolAddress((void**)&k,    g_k);
    cudaGetSymbolAddress((void**)&v,    g_v);
    cudaGetSymbolAddress((void**)&attn, g_attn);
    cudaGetSymbolAddress((void**)&h,    g_h);
    cudaGetSymbolAddress((void**)&u1,   g_u1);
    cudaGetSymbolAddress((void**)&u3,   g_u3);
    cudaGetSymbolAddress((void**)&outrows, g_outrows);
    cudaGetSymbolAddress((void**)&part, g_part);
    cudaGetSymbolAddress((void**)&ah,   g_ah);
    cudaGetSymbolAddress((void**)&al,   g_al);
    cudaGetSymbolAddress((void**)&whqkv, g_whqkv);
    cudaGetSymbolAddress((void**)&wlqkv, g_wlqkv);
    cudaGetSymbolAddress((void**)&who,  g_who);
    cudaGetSymbolAddress((void**)&wlo_, g_wlo);
    cudaGetSymbolAddress((void**)&wh13, g_wh13);
    cudaGetSymbolAddress((void**)&wl13, g_wl13);
    cudaGetSymbolAddress((void**)&whw2, g_whw2);
    cudaGetSymbolAddress((void**)&wlw2, g_wlw2);

    int attn_smem = (QT*QS_STRIDE + KC*QS_STRIDE + QT*SC_STRIDE) * 4;
    cudaFuncSetAttribute(attn_kernel, cudaFuncAttributeMaxDynamicSharedMemorySize, attn_smem);
    cudaFuncSetAttribute(hgemm, cudaFuncAttributeMaxDynamicSharedMemorySize, GEMM_SMEM);

    const int MTILES_SEL = RSEL / BM;              // 4
    const int MTILES_TOT = (RTOT + BM - 1) / BM;   // 5
    size_t dd2 = (size_t)DD * DD;
    size_t dh  = (size_t)DD * HIDDEN;

    // ---- weight pre-split ----
    convW_kernel<<<dim3(DD/64, DD/64), 256>>>(wq, whqkv,        wlqkv,        DD, DD);
    convW_kernel<<<dim3(DD/64, DD/64), 256>>>(wk, whqkv + dd2,  wlqkv + dd2,  DD, DD);
    convW_kernel<<<dim3(DD/64, DD/64), 256>>>(wv, whqkv + 2*dd2,wlqkv + 2*dd2,DD, DD);
    convW_kernel<<<dim3(DD/64, DD/64), 256>>>(wo, who, wlo_, DD, DD);
    convW_kernel<<<dim3(HIDDEN/64, DD/64), 256>>>(w1, wh13,      wl13,      DD, HIDDEN);
    convW_kernel<<<dim3(HIDDEN/64, DD/64), 256>>>(w3, wh13 + dh, wl13 + dh, DD, HIDDEN);
    convW_kernel<<<dim3(DD/64, HIDDEN/64), 256>>>(w2, whw2, wlw2, HIDDEN, DD);

    // 1. router (exact fp32 -> identical top-k)
    router_kernel<<<BB*SS, 256>>>(x, router_w, tw, out, off_tw, osz);
    // 2. top-k
    topk_kernel<<<BB, 1024>>>(tw, idx, out, off_idx, osz);
    // 3. rank map
    rank_init<<<(BB*SS + 255)/256, 256>>>(rank);
    rank_set<<<(RSEL + 255)/256, 256>>>(idx, rank);
    // 4. gather + rmsnorm(attn), fused hi/lo split
    rmsnorm_gather_h<<<RSEL, 256>>>(x, idx, attn_nw, ah, al);
    // 5. QKV projections: split-K=2, 3 weights -> 6 z-slices
    {
        size_t perW = (size_t)RSEL * DD;
        hgemm<<<dim3(DD/BN, MTILES_SEL, 6), 256, GEMM_SMEM>>>(
            ah, al, whqkv, wlqkv, part, RSEL, DD, DD, 2);
        reduceN_kernel<<<dim3((unsigned)((perW/4 + 255)/256), 3), 256>>>(
            part, q, k, v, 2, perW);
    }
    // 6. rotary
    rotary_kernel<<<RSEL, 256>>>(q, k, idx, freqs, start_p);
    // 7. attention
    attn_kernel<<<dim3(TOPK/QT, HH, BB), 256, attn_smem>>>(q, k, v, attn);
    // 8. shared row = mean V
    meanv_kernel<<<dim3(HH, BB), HD>>>(v, attn);
    // 9. wo projection (split-K=4) + add x
    convA_kernel<<<RTOT, 256>>>(attn, ah, al, DD);
    {
        size_t perW = (size_t)RTOT * DD;
        hgemm<<<dim3(DD/BN, MTILES_TOT, 4), 256, GEMM_SMEM>>>(
            ah, al, who, wlo_, part, RTOT, DD, DD, 4);
        reduceN_kernel<<<dim3((unsigned)((perW/4 + 255)/256), 1), 256>>>(
            part, h, h, h, 4, perW);
    }
    addx_kernel<<<RSEL, 256>>>(x, idx, h);
    // 10. ffn rmsnorm, fused hi/lo split
    rmsnorm_rows_h<<<RTOT, 256>>>(h, ffn_nw, ah, al);
    // 11. FFN13: split-K=2, 2 weights -> 4 z-slices
    {
        size_t perW = (size_t)RTOT * HIDDEN;
        hgemm<<<dim3(HIDDEN/BN, MTILES_TOT, 4), 256, GEMM_SMEM>>>(
            ah, al, wh13, wl13, part, RTOT, DD, HIDDEN, 2);
        reduceN_kernel<<<dim3((unsigned)((perW/4 + 255)/256), 2), 256>>>(
            part, u1, u3, u3, 2, perW);
    }
    {
        size_t n = (size_t)RTOT * HIDDEN;
        silu_mul_h<<<(unsigned)((n/2 + 255)/256), 256>>>(u1, u3, ah, al, n);
    }
    // w2: split-K=8
    {
        size_t perW = (size_t)RTOT * DD;
        hgemm<<<dim3(DD/BN, MTILES_TOT, 8), 256, GEMM_SMEM>>>(
            ah, al, whw2, wlw2, part, RTOT, HIDDEN, DD, 8);
        reduceN_kernel<<<dim3((unsigned)((perW/4 + 255)/256), 1), 256>>>(
            part, outrows, outrows, outrows, 8, perW);
    }
    // 12. scatter
    scatter_out<<<BB*SS, 256>>>(outrows, rank, out);
}

// round 16
// speedup vs baseline: 2.6584x; 1.0066x over previous
#include <cuda_runtime.h>
#include <cuda_bf16.h>
#include <cuda_fp16.h>
#include <math.h>
#include <cstdint>

// Problem constants
#define BB 2
#define SS 2048
#define DD 2048
#define HH 16
#define HD 128
#define TOPK 256
#define HIDDEN 8192
#define RSEL (BB*TOPK)      // 512 selected rows total
#define RTOT (RSEL + BB)    // + 1 shared row per batch = 514
#define EPS 1e-6f

// ---------------- scratch (static device globals; no allocs allowed) ----------------
__device__ float g_tw[BB*SS];
__device__ int   g_idx[BB*TOPK];
__device__ int   g_rank[BB*SS];
__device__ float g_q[RSEL*DD];
__device__ float g_k[RSEL*DD];
__device__ float g_v[RSEL*DD];
__device__ float g_attn[RTOT*DD];
__device__ float g_h[RTOT*DD];
__device__ float g_outrows[RTOT*DD];
// fp16 hi/lo pre-split buffers
__device__ __half g_ah[RTOT*HIDDEN];
__device__ __half g_al[RTOT*HIDDEN];
__device__ __half g_whqkv[3u*DD*DD];
__device__ __half g_wlqkv[3u*DD*DD];
__device__ __half g_who[DD*DD];
__device__ __half g_wlo[DD*DD];
__device__ __half g_wh13[2u*DD*HIDDEN];
__device__ __half g_wl13[2u*DD*HIDDEN];
__device__ __half g_whw2[(size_t)DD*HIDDEN];
__device__ __half g_wlw2[(size_t)DD*HIDDEN];
__device__ float  g_part[4u*RTOT*HIDDEN];   // max: FFN13 2w x 2s x RTOT x HIDDEN

// ================= helpers =================
__device__ __forceinline__ uint32_t smem_u32(const void* p) {
    uint32_t a;
    asm("{ .reg .u64 t; cvta.to.shared.u64 t, %1; cvt.u32.u64 %0, t; }" : "=r"(a) : "l"(p));
    return a;
}
__device__ __forceinline__ void cpa16(uint32_t dst, const void* src, int sz) {
    asm volatile("cp.async.cg.shared.global [%0], [%1], 16, %2;" :: "r"(dst), "l"(src), "r"(sz) : "memory");
}
#define CP_COMMIT() asm volatile("cp.async.commit_group;" ::: "memory")

__device__ __forceinline__ void mma_f16(float* cc, const uint32_t* a, const uint32_t* b) {
    asm volatile(
        "mma.sync.aligned.m16n8k16.row.col.f32.f16.f16.f32 "
        "{%0,%1,%2,%3},{%4,%5,%6,%7},{%8,%9},{%0,%1,%2,%3};"
        : "+f"(cc[0]), "+f"(cc[1]), "+f"(cc[2]), "+f"(cc[3])
        : "r"(a[0]), "r"(a[1]), "r"(a[2]), "r"(a[3]), "r"(b[0]), "r"(b[1]));
}
// packed split: two fp32 -> hi half2 + lo half2 (round-nearest, identical to scalar path)
__device__ __forceinline__ void h2split(float r0, float r1, uint32_t& hw, uint32_t& lw) {
    __half2 hh = __floats2half2_rn(r0, r1);
    float2 hf = __half22float2(hh);
    __half2 ll = __floats2half2_rn(r0 - hf.x, r1 - hf.y);
    hw = *reinterpret_cast<uint32_t*>(&hh);
    lw = *reinterpret_cast<uint32_t*>(&ll);
}
__device__ __forceinline__ void hsplit2_store(float r0, float r1, __half* Ah, __half* Al, size_t i) {
    uint32_t hw, lw;
    h2split(r0, r1, hw, lw);
    *(uint32_t*)(Ah + i) = hw;
    *(uint32_t*)(Al + i) = lw;
}

// ================= conversion kernels =================
// A[M][K] fp32 -> Ah, Al [M][K] half
__global__ void convA_kernel(const float* __restrict__ A, __half* __restrict__ Ah,
                             __half* __restrict__ Al, int K) {
    int row = blockIdx.x;
    const float* ar = A + (size_t)row * K;
    for (int base = threadIdx.x * 8; base < K; base += 2048) {
        float4 v0 = *(const float4*)(ar + base);
        float4 v1 = *(const float4*)(ar + base + 4);
        uint32_t wh[4], wl[4];
        h2split(v0.x, v0.y, wh[0], wl[0]);
        h2split(v0.z, v0.w, wh[1], wl[1]);
        h2split(v1.x, v1.y, wh[2], wl[2]);
        h2split(v1.z, v1.w, wh[3], wl[3]);
        *(uint4*)(Ah + (size_t)row * K + base) = make_uint4(wh[0], wh[1], wh[2], wh[3]);
        *(uint4*)(Al + (size_t)row * K + base) = make_uint4(wl[0], wl[1], wl[2], wl[3]);
    }
}

// W[K][N] fp32 -> Wh, Wl [N][K] half (transposed). 64 n x 128 k per block.
__global__ void convW_kernel(const float* __restrict__ W, __half* __restrict__ Wh,
                             __half* __restrict__ Wl, int K, int N) {
    __shared__ float ts[128][65];
    int t = threadIdx.x;
    int n0 = blockIdx.x * 64, k0 = blockIdx.y * 128;
    #pragma unroll
    for (int i = 0; i < 32; i++) {
        int idx = t + 256 * i;
        int kk = idx >> 6, nn = idx & 63;
        ts[kk][nn] = W[(size_t)(k0 + kk) * N + n0 + nn];
    }
    __syncthreads();
    int j = t >> 2, ch = t & 3;          // j = local n, ch selects 16-k group within each 64-k half
    int n = n0 + j;
    #pragma unroll
    for (int half = 0; half < 2; half++) {
        int kb = half * 64 + ch * 16;
        uint32_t wh[8], wl[8];
        #pragma unroll
        for (int w = 0; w < 8; w++) {
            h2split(ts[kb + 2*w][j], ts[kb + 2*w + 1][j], wh[w], wl[w]);
        }
        size_t o = (size_t)n * K + k0 + kb;
        *(uint4*)(Wh + o)     = make_uint4(wh[0], wh[1], wh[2], wh[3]);
        *(uint4*)(Wh + o + 8) = make_uint4(wh[4], wh[5], wh[6], wh[7]);
        *(uint4*)(Wl + o)     = make_uint4(wl[0], wl[1], wl[2], wl[3]);
        *(uint4*)(Wl + o + 8) = make_uint4(wl[4], wl[5], wl[6], wl[7]);
    }
}

// ================= fp16x3 GEMM, pre-split operands, generalized split-K =================
#define BM 128
#define BN 128
#define BKK 32
#define HPART 16384
#define HSTAGE (4*HPART)
#define GEMM_SMEM (2*HSTAGE)

__device__ __forceinline__ uint32_t hswz(int row, int u, int c4) {
    return (uint32_t)(row * 128 + ((u ^ (row & 7)) << 4) + c4);
}

__device__ __forceinline__ void h_load_stage(
    const __half* __restrict__ Ah, const __half* __restrict__ Al,
    const __half* __restrict__ Bh, const __half* __restrict__ Bl,
    uint32_t sbase, int buf, int bm, int bn, int k0, int M, int K, int tid)
{
    uint32_t st = sbase + (uint32_t)buf * HSTAGE;
    #pragma unroll
    for (int i = 0; i < 2; i++) {
        int g = tid + 256 * i;
        int row = g >> 2, u = g & 3;
        uint32_t doff = (uint32_t)(row * 128 + ((u ^ (row & 7)) << 4));
        int gm = bm + row;
        int sz = (gm < M) ? 16 : 0;
        int gmc = (gm < M) ? gm : (M - 1);
        size_t ga = (size_t)gmc * K + k0 + u * 8;
        cpa16(st + doff,           Ah + ga, sz);
        cpa16(st + HPART + doff,   Al + ga, sz);
        size_t gb = (size_t)(bn + row) * K + k0 + u * 8;
        cpa16(st + 2*HPART + doff, Bh + gb, 16);
        cpa16(st + 3*HPART + doff, Bl + gb, 16);
    }
    CP_COMMIT();
}

// blockIdx.z = w*nsplit + s. Writes partial slice part[z][M][N].
__global__ void __launch_bounds__(256) hgemm(
    const __half* __restrict__ Ah, const __half* __restrict__ Al,
    const __half* __restrict__ Bh, const __half* __restrict__ Bl,
    float* __restrict__ part, int M, int K, int N, int nsplit)
{
    extern __shared__ char sm8[];
    int z = blockIdx.z;
    int w = z / nsplit, s = z % nsplit;
    const __half* Bh_ = Bh + (size_t)w * N * K;
    const __half* Bl_ = Bl + (size_t)w * N * K;
    float* C = part + (size_t)z * M * N;
    int Keff = K / nsplit;
    int kbase = s * Keff;

    uint32_t sbase = smem_u32(sm8);
    int tid = threadIdx.x;
    int bm = blockIdx.y * BM, bn = blockIdx.x * BN;
    int lane = tid & 31, wid = tid >> 5;
    int r = lane >> 2, c = lane & 3;
    int c4 = c * 4;
    int m_base = (wid >> 2) * 64;
    int n_base = (wid & 3) * 32;

    float acc[4][4][4];
    #pragma unroll
    for (int mt = 0; mt < 4; mt++)
        #pragma unroll
        for (int nt = 0; nt < 4; nt++)
            #pragma unroll
            for (int q = 0; q < 4; q++) acc[mt][nt][q] = 0.f;

    int T = Keff / BKK;
    h_load_stage(Ah, Al, Bh_, Bl_, sbase, 0, bm, bn, kbase, M, K, tid);

    for (int i = 0; i < T; i++) {
        int buf = i & 1;
        if (i + 1 < T) {
            h_load_stage(Ah, Al, Bh_, Bl_, sbase, buf ^ 1, bm, bn, kbase + (i + 1) * BKK, M, K, tid);
            asm volatile("cp.async.wait_group 1;" ::: "memory");
        } else {
            asm volatile("cp.async.wait_group 0;" ::: "memory");
        }
        __syncthreads();

        const char* sAh = sm8 + buf * HSTAGE;
        const char* sAl = sAh + HPART;
        const char* sBh = sAh + 2*HPART;
        const char* sBl = sAh + 3*HPART;
        #pragma unroll
        for (int ks = 0; ks < 2; ks++) {
            int u0 = 2 * ks, u1 = 2 * ks + 1;
            uint32_t ah[4][4], al[4][4];
            #pragma unroll
            for (int mt = 0; mt < 4; mt++) {
                int row0 = m_base + mt * 16 + r;
                ah[mt][0] = *(const uint32_t*)(sAh + hswz(row0,     u0, c4));
                ah[mt][1] = *(const uint32_t*)(sAh + hswz(row0 + 8, u0, c4));
                ah[mt][2] = *(const uint32_t*)(sAh + hswz(row0,     u1, c4));
                ah[mt][3] = *(const uint32_t*)(sAh + hswz(row0 + 8, u1, c4));
                al[mt][0] = *(const uint32_t*)(sAl + hswz(row0,     u0, c4));
                al[mt][1] = *(const uint32_t*)(sAl + hswz(row0 + 8, u0, c4));
                al[mt][2] = *(const uint32_t*)(sAl + hswz(row0,     u1, c4));
                al[mt][3] = *(const uint32_t*)(sAl + hswz(row0 + 8, u1, c4));
            }
            uint32_t bh[4][2], bl[4][2];
            #pragma unroll
            for (int nt = 0; nt < 4; nt++) {
                int n = n_base + nt * 8 + r;
                bh[nt][0] = *(const uint32_t*)(sBh + hswz(n, u0, c4));
                bh[nt][1] = *(const uint32_t*)(sBh + hswz(n, u1, c4));
                bl[nt][0] = *(const uint32_t*)(sBl + hswz(n, u0, c4));
                bl[nt][1] = *(const uint32_t*)(sBl + hswz(n, u1, c4));
            }
            #pragma unroll
            for (int mt = 0; mt < 4; mt++)
                #pragma unroll
                for (int nt = 0; nt < 4; nt++) {
                    mma_f16(acc[mt][nt], al[mt], bh[nt]);
                    mma_f16(acc[mt][nt], ah[mt], bl[nt]);
                    mma_f16(acc[mt][nt], ah[mt], bh[nt]);
                }
        }
        __syncthreads();
    }

    #pragma unroll
    for (int mt = 0; mt < 4; mt++) {
        int row0 = bm + m_base + mt * 16 + r;
        #pragma unroll
        for (int nt = 0; nt < 4; nt++) {
            int col = bn + n_base + nt * 8 + c * 2;
            if (row0 < M) {
                float2 v = make_float2(acc[mt][nt][0], acc[mt][nt][1]);
                *(float2*)(C + (size_t)row0 * N + col) = v;
            }
            if (row0 + 8 < M) {
                float2 v = make_float2(acc[mt][nt][2], acc[mt][nt][3]);
                *(float2*)(C + (size_t)(row0 + 8) * N + col) = v;
            }
        }
    }
}

// generic reduce (used for w2 only now)
__global__ void reduceN_kernel(const float* __restrict__ part,
                               float* __restrict__ dst, int nsplit, size_t perW) {
    size_t i = ((size_t)blockIdx.x * 256 + threadIdx.x) * 4;
    if (i < perW) {
        float4 acc = *(const float4*)(part + i);
        for (int s = 1; s < nsplit; s++) {
            float4 p = *(const float4*)(part + (size_t)s * perW + i);
            acc.x += p.x; acc.y += p.y; acc.z += p.z; acc.w += p.w;
        }
        *(float4*)(dst + i) = acc;
    }
}

// fused QKV reduce (nsplit=2) + rotary
__global__ void qkv_rotary_kernel(const float* __restrict__ part,
                                  const int* __restrict__ gidx,
                                  const float* __restrict__ freqs,
                                  const int* __restrict__ startp,
                                  float* __restrict__ q, float* __restrict__ k,
                                  float* __restrict__ v) {
    int r = blockIdx.x;
    size_t perW = (size_t)RSEL * DD;
    size_t ro = (size_t)r * DD;
    const float* pq0 = part + ro;            const float* pq1 = pq0 + perW;
    const float* pk0 = part + 2*perW + ro;   const float* pk1 = pk0 + perW;
    const float* pv0 = part + 4*perW + ro;   const float* pv1 = pv0 + perW;
    int pos = startp[0] + gidx[r];
    const float* f = freqs + (size_t)pos * HD;
    for (int e = threadIdx.x; e < DD/2; e += 256) {
        int hp = e & 63;
        float cc = f[hp*2], sn = f[hp*2+1];
        int i0 = e * 2;
        float q0 = pq0[i0] + pq1[i0];
        float q1 = pq0[i0+1] + pq1[i0+1];
        q[ro + i0]   = q0*cc - q1*sn;
        q[ro + i0+1] = q0*sn + q1*cc;
        float k0 = pk0[i0] + pk1[i0];
        float k1 = pk0[i0+1] + pk1[i0+1];
        k[ro + i0]   = k0*cc - k1*sn;
        k[ro + i0+1] = k0*sn + k1*cc;
        v[ro + i0]   = pv0[i0] + pv1[i0];
        v[ro + i0+1] = pv0[i0+1] + pv1[i0+1];
    }
}

// fused wo reduce (nsplit=4) + add masked x
__global__ void wo_reduce_addx(const float* __restrict__ part, const float* __restrict__ x,
                               const int* __restrict__ gidx, float* __restrict__ h) {
    int r = blockIdx.x;
    size_t perW = (size_t)RTOT * DD;
    size_t ro = (size_t)r * DD;
    const float* p0 = part + ro;
    const float* xr = nullptr;
    if (r < RSEL) {
        int b = r / TOPK;
        xr = x + ((size_t)b * SS + gidx[r]) * DD;
    }
    for (int c = threadIdx.x * 4; c < DD; c += 1024) {
        float4 a = *(const float4*)(p0 + c);
        float4 b1 = *(const float4*)(p0 + perW + c);
        float4 b2 = *(const float4*)(p0 + 2*perW + c);
        float4 b3 = *(const float4*)(p0 + 3*perW + c);
        float4 acc = make_float4(((a.x+b1.x)+b2.x)+b3.x, ((a.y+b1.y)+b2.y)+b3.y,
                                 ((a.z+b1.z)+b2.z)+b3.z, ((a.w+b1.w)+b2.w)+b3.w);
        if (xr) {
            float4 xv = *(const float4*)(xr + c);
            acc.x += xv.x; acc.y += xv.y; acc.z += xv.z; acc.w += xv.w;
        }
        *(float4*)(h + ro + c) = acc;
    }
}

// fused FFN13 reduce (nsplit=2 each) + silu + hi/lo split
__global__ void ffn_silu_split(const float* __restrict__ part,
                               __half* __restrict__ Ah, __half* __restrict__ Al) {
    size_t perW = (size_t)RTOT * HIDDEN;
    size_t i = ((size_t)blockIdx.x * 256 + threadIdx.x) * 2;
    if (i < perW) {
        float2 a0 = *(const float2*)(part + i);
        float2 a1 = *(const float2*)(part + perW + i);
        float2 b0 = *(const float2*)(part + 2*perW + i);
        float2 b1 = *(const float2*)(part + 3*perW + i);
        float u1x = a0.x + a1.x, u1y = a0.y + a1.y;
        float u3x = b0.x + b1.x, u3y = b0.y + b1.y;
        float r0 = u1x / (1.f + expf(-u1x)) * u3x;
        float r1 = u1y / (1.f + expf(-u1y)) * u3y;
        hsplit2_store(r0, r1, Ah, Al, i);
    }
}

// ---------------- 1. router ----------------
__global__ void router_kernel(const float* __restrict__ x, const float* __restrict__ rw,
                              float* __restrict__ tw, float* __restrict__ dout,
                              size_t off_tw, size_t out_size) {
    int tok = blockIdx.x;
    __shared__ float red[256];
    float s = 0.f;
    const float* xr = x + (size_t)tok * DD;
    for (int c = threadIdx.x; c < DD; c += 256) s += xr[c] * rw[c];
    red[threadIdx.x] = s; __syncthreads();
    for (int o = 128; o > 0; o >>= 1) {
        if (threadIdx.x < o) red[threadIdx.x] += red[threadIdx.x + o];
        __syncthreads();
    }
    if (threadIdx.x == 0) {
        tw[tok] = red[0];
        if (off_tw + (size_t)tok < out_size) dout[off_tw + tok] = red[0];
    }
}

// ---------------- 2. top-k ----------------
__global__ void topk_kernel(const float* __restrict__ tw, int* __restrict__ gidx,
                            float* __restrict__ dout, size_t off_idx, size_t out_size) {
    __shared__ float v[SS];
    __shared__ int   id[SS];
    int b = blockIdx.x;
    int t = threadIdx.x;
    for (int i = t; i < SS; i += 1024) { v[i] = tw[b*SS + i]; id[i] = i; }
    __syncthreads();
    for (int k = 2; k <= SS; k <<= 1) {
        for (int j = k >> 1; j > 0; j >>= 1) {
            for (int i = t; i < SS; i += 1024) {
                int ixj = i ^ j;
                if (ixj > i) {
                    bool up = ((i & k) == 0);
                    float va = v[i], vb = v[ixj];
                    int   ia = id[i], ib = id[ixj];
                    bool aBeforeB = (va > vb) || (va == vb && ia < ib);
                    bool sw = up ? !aBeforeB : aBeforeB;
                    if (sw) { v[i]=vb; v[ixj]=va; id[i]=ib; id[ixj]=ia; }
                }
            }
            __syncthreads();
        }
    }
    for (int i = t; i < TOPK; i += 1024) {
        gidx[b*TOPK + i] = id[i];
        size_t o = off_idx + (size_t)b*TOPK + i;
        if (o < out_size) dout[o] = (float)id[i];
    }
}

// ---------------- 3. rank map ----------------
__global__ void rank_init(int* __restrict__ rank) {
    int i = blockIdx.x*256 + threadIdx.x;
    if (i < BB*SS) rank[i] = -1;
}
__global__ void rank_set(const int* __restrict__ gidx, int* __restrict__ rank) {
    int r = blockIdx.x*256 + threadIdx.x;
    if (r < RSEL) {
        int b = r / TOPK;
        rank[b*SS + gidx[r]] = r % TOPK;
    }
}

// ---------------- 4. gather + rmsnorm -> fused hi/lo split ----------------
__global__ void rmsnorm_gather_h(const float* __restrict__ x, const int* __restrict__ gidx,
                                 const float* __restrict__ w,
                                 __half* __restrict__ Ah, __half* __restrict__ Al) {
    int r = blockIdx.x;
    int b = r / TOPK;
    int pos = gidx[r];
    const float* xr = x + ((size_t)b*SS + pos) * DD;
    __shared__ float red[256];
    float s = 0.f;
    for (int c = threadIdx.x; c < DD; c += 256) { float v = xr[c]; s += v*v; }
    red[threadIdx.x] = s; __syncthreads();
    for (int o = 128; o > 0; o >>= 1) {
        if (threadIdx.x < o) red[threadIdx.x] += red[threadIdx.x + o];
        __syncthreads();
    }
    float rms = rsqrtf(red[0] / (float)DD + EPS);
    size_t base = (size_t)r * DD;
    for (int c = threadIdx.x * 2; c < DD; c += 512) {
        float r0 = xr[c] * rms * w[c];
        float r1 = xr[c+1] * rms * w[c+1];
        hsplit2_store(r0, r1, Ah, Al, base + c);
    }
}

__global__ void rmsnorm_rows_h(const float* __restrict__ in, const float* __restrict__ w,
                               __half* __restrict__ Ah, __half* __restrict__ Al) {
    int r = blockIdx.x;
    const float* xr = in + (size_t)r * DD;
    __shared__ float red[256];
    float s = 0.f;
    for (int c = threadIdx.x; c < DD; c += 256) { float v = xr[c]; s += v*v; }
    red[threadIdx.x] = s; __syncthreads();
    for (int o = 128; o > 0; o >>= 1) {
        if (threadIdx.x < o) red[threadIdx.x] += red[threadIdx.x + o];
        __syncthreads();
    }
    float rms = rsqrtf(red[0] / (float)DD + EPS);
    size_t base = (size_t)r * DD;
    for (int c = threadIdx.x * 2; c < DD; c += 512) {
        float r0 = xr[c] * rms * w[c];
        float r1 = xr[c+1] * rms * w[c+1];
        hsplit2_store(r0, r1, Ah, Al, base + c);
    }
}

// ---------------- 7. attention ----------------
#define QT 64
#define KC 64
#define QS_STRIDE 129
#define SC_STRIDE 257
__global__ void attn_kernel(const float* __restrict__ q, const float* __restrict__ k,
                            const float* __restrict__ v, float* __restrict__ attn) {
    extern __shared__ float smf[];
    float* qs = smf;
    float* kt = qs + QT*QS_STRIDE;
    float* sc = kt + KC*QS_STRIDE;
    int qt = blockIdx.x, h = blockIdx.y, b = blockIdx.z;
    int t = threadIdx.x;
    int rb = b * TOPK;
    for (int l = t; l < QT*HD; l += 256) {
        int qi = l / HD, d = l % HD;
        qs[qi*QS_STRIDE + d] = q[((size_t)(rb + qt*QT + qi))*DD + h*HD + d];
    }
    const float scale = 0.08838834764831845f;
    int qi = t >> 2;
    {
        int kj0 = (t & 3) * 16;
        for (int kc = 0; kc < TOPK/KC; kc++) {
            __syncthreads();
            for (int l = t; l < KC*HD; l += 256) {
                int kj = l / HD, d = l % HD;
                kt[kj*QS_STRIDE + d] = k[((size_t)(rb + kc*KC + kj))*DD + h*HD + d];
            }
            __syncthreads();
            float acc[16];
            #pragma unroll
            for (int n = 0; n < 16; n++) acc[n] = 0.f;
            for (int d = 0; d < HD; d++) {
                float qv = qs[qi*QS_STRIDE + d];
                #pragma unroll
                for (int n = 0; n < 16; n++)
                    acc[n] += qv * kt[(kj0+n)*QS_STRIDE + d];
            }
            #pragma unroll
            for (int n = 0; n < 16; n++)
                sc[qi*SC_STRIDE + kc*KC + kj0 + n] = acc[n] * scale;
        }
    }
    __syncthreads();
    if (t < QT) {
        float m = -1e30f;
        for (int j = 0; j < TOPK; j++) m = fmaxf(m, sc[t*SC_STRIDE + j]);
        float s = 0.f;
        for (int j = 0; j < TOPK; j++) {
            float e = expf(sc[t*SC_STRIDE + j] - m);
            sc[t*SC_STRIDE + j] = e; s += e;
        }
        float inv = 1.f / s;
        for (int j = 0; j < TOPK; j++) sc[t*SC_STRIDE + j] *= inv;
    }
    __syncthreads();
    int d0 = (t & 3) * 32;
    float oacc[32];
    #pragma unroll
    for (int i = 0; i < 32; i++) oacc[i] = 0.f;
    for (int kc = 0; kc < TOPK/KC; kc++) {
        __syncthreads();
        for (int l = t; l < KC*HD; l += 256) {
            int kj = l / HD, d = l % HD;
            kt[kj*QS_STRIDE + d] = v[((size_t)(rb + kc*KC + kj))*DD + h*HD + d];
        }
        __syncthreads();
        for (int j = 0; j < KC; j++) {
            float p = sc[qi*SC_STRIDE + kc*KC + j];
            #pragma unroll
            for (int dd = 0; dd < 32; dd++)
                oacc[dd] += p * kt[j*QS_STRIDE + d0 + dd];
        }
    }
    float* orow = attn + ((size_t)(rb + qt*QT + qi))*DD + h*HD + d0;
    #pragma unroll
    for (int dd = 0; dd < 32; dd++) orow[dd] = oacc[dd];
}

// ---------------- 8. mean V ----------------
__global__ void meanv_kernel(const float* __restrict__ v, float* __restrict__ attn) {
    int h = blockIdx.x, b = blockIdx.y;
    int d = threadIdx.x;
    float s = 0.f;
    for (int j = 0; j < TOPK; j++)
        s += v[((size_t)(b*TOPK + j))*DD + h*HD + d];
    attn[((size_t)(RSEL + b))*DD + h*HD + d] = s * (1.f / TOPK);
}

// ---------------- 11. scatter ----------------
__global__ void scatter_out(const float* __restrict__ rows, const int* __restrict__ rank,
                            float* __restrict__ dout) {
    int tok = blockIdx.x;
    int b = tok / SS;
    int rk = rank[tok];
    int srow = (rk >= 0) ? (b*TOPK + rk) : (RSEL + b);
    const float4* s4 = (const float4*)(rows + (size_t)srow * DD);
    float4* d4 = (float4*)(dout + (size_t)tok * DD);
    for (int c = threadIdx.x; c < DD/4; c += 256) d4[c] = s4[c];
}

// ---------------- launch ----------------
extern "C" void kernel_launch(void* const* d_in, const int* in_sizes, int n_in,
                              void* d_out, int out_size) {
    const float* x        = (const float*)d_in[0];
    const int*   start_p  = (const int*)  d_in[1];
    const float* freqs    = (const float*)d_in[2];
    const float* router_w = (const float*)d_in[3];
    const float* wq       = (const float*)d_in[4];
    const float* wk       = (const float*)d_in[5];
    const float* wv       = (const float*)d_in[6];
    const float* wo       = (const float*)d_in[7];
    const float* w1       = (const float*)d_in[8];
    const float* w2       = (const float*)d_in[9];
    const float* w3       = (const float*)d_in[10];
    const float* attn_nw  = (const float*)d_in[11];
    const float* ffn_nw   = (const float*)d_in[12];
    float* out = (float*)d_out;

    size_t off_tw  = (size_t)BB*SS*DD;
    size_t off_idx = off_tw + (size_t)BB*SS;
    size_t osz = (size_t)out_size;

    float *tw, *q, *k, *v, *attn, *h, *outrows, *part;
    int *idx, *rank;
    __half *ah, *al, *whqkv, *wlqkv, *who, *wlo_, *wh13, *wl13, *whw2, *wlw2;
    cudaGetSymbolAddress((void**)&tw,   g_tw);
    cudaGetSymbolAddress((void**)&idx,  g_idx);
    cudaGetSymbolAddress((void**)&rank, g_rank);
    cudaGetSymbolAddress((void**)&q,    g_q);
    cudaGetSymbolAddress((void**)&k,    g_k);
    cudaGetSymbolAddress((void**)&v,    g_v);
    cudaGetSymbolAddress((void**)&attn, g_attn);
    cudaGetSymbolAddress((void**)&h,    g_h);
    cudaGetSymbolAddress((void**)&outrows, g_outrows);
    cudaGetSymbolAddress((void**)&part, g_part);
    cudaGetSymbolAddress((void**)&ah,   g_ah);
    cudaGetSymbolAddress((void**)&al,   g_al);
    cudaGetSymbolAddress((void**)&whqkv, g_whqkv);
    cudaGetSymbolAddress((void**)&wlqkv, g_wlqkv);
    cudaGetSymbolAddress((void**)&who,  g_who);
    cudaGetSymbolAddress((void**)&wlo_, g_wlo);
    cudaGetSymbolAddress((void**)&wh13, g_wh13);
    cudaGetSymbolAddress((void**)&wl13, g_wl13);
    cudaGetSymbolAddress((void**)&whw2, g_whw2);
    cudaGetSymbolAddress((void**)&wlw2, g_wlw2);

    int attn_smem = (QT*QS_STRIDE + KC*QS_STRIDE + QT*SC_STRIDE) * 4;
    cudaFuncSetAttribute(attn_kernel, cudaFuncAttributeMaxDynamicSharedMemorySize, attn_smem);
    cudaFuncSetAttribute(hgemm, cudaFuncAttributeMaxDynamicSharedMemorySize, GEMM_SMEM);

    const int MTILES_SEL = RSEL / BM;              // 4
    const int MTILES_TOT = (RTOT + BM - 1) / BM;   // 5
    size_t dd2 = (size_t)DD * DD;
    size_t dh  = (size_t)DD * HIDDEN;

    // ---- weight pre-split (hi/lo fp16, transposed to [N][K]) ----
    convW_kernel<<<dim3(DD/64, DD/128), 256>>>(wq, whqkv,        wlqkv,        DD, DD);
    convW_kernel<<<dim3(DD/64, DD/128), 256>>>(wk, whqkv + dd2,  wlqkv + dd2,  DD, DD);
    convW_kernel<<<dim3(DD/64, DD/128), 256>>>(wv, whqkv + 2*dd2,wlqkv + 2*dd2,DD, DD);
    convW_kernel<<<dim3(DD/64, DD/128), 256>>>(wo, who, wlo_, DD, DD);
    convW_kernel<<<dim3(HIDDEN/64, DD/128), 256>>>(w1, wh13,      wl13,      DD, HIDDEN);
    convW_kernel<<<dim3(HIDDEN/64, DD/128), 256>>>(w3, wh13 + dh, wl13 + dh, DD, HIDDEN);
    convW_kernel<<<dim3(DD/64, HIDDEN/128), 256>>>(w2, whw2, wlw2, HIDDEN, DD);

    // 1. router (exact fp32 -> identical top-k)
    router_kernel<<<BB*SS, 256>>>(x, router_w, tw, out, off_tw, osz);
    // 2. top-k
    topk_kernel<<<BB, 1024>>>(tw, idx, out, off_idx, osz);
    // 3. rank map
    rank_init<<<(BB*SS + 255)/256, 256>>>(rank);
    rank_set<<<(RSEL + 255)/256, 256>>>(idx, rank);
    // 4. gather + rmsnorm(attn), fused hi/lo split
    rmsnorm_gather_h<<<RSEL, 256>>>(x, idx, attn_nw, ah, al);
    // 5. QKV projections: split-K=2, 3 weights -> 6 z-slices; fused reduce+rotary
    hgemm<<<dim3(DD/BN, MTILES_SEL, 6), 256, GEMM_SMEM>>>(
        ah, al, whqkv, wlqkv, part, RSEL, DD, DD, 2);
    qkv_rotary_kernel<<<RSEL, 256>>>(part, idx, freqs, start_p, q, k, v);
    // 7. attention
    attn_kernel<<<dim3(TOPK/QT, HH, BB), 256, attn_smem>>>(q, k, v, attn);
    // 8. shared row = mean V
    meanv_kernel<<<dim3(HH, BB), HD>>>(v, attn);
    // 9. wo projection (split-K=4), fused reduce + add masked x
    convA_kernel<<<RTOT, 256>>>(attn, ah, al, DD);
    hgemm<<<dim3(DD/BN, MTILES_TOT, 4), 256, GEMM_SMEM>>>(
        ah, al, who, wlo_, part, RTOT, DD, DD, 4);
    wo_reduce_addx<<<RTOT, 256>>>(part, x, idx, h);
    // 10. ffn rmsnorm, fused hi/lo split
    rmsnorm_rows_h<<<RTOT, 256>>>(h, ffn_nw, ah, al);
    // 11. FFN13: split-K=2, 2 weights -> 4 z-slices; fused reduce+silu+split
    hgemm<<<dim3(HIDDEN/BN, MTILES_TOT, 4), 256, GEMM_SMEM>>>(
        ah, al, wh13, wl13, part, RTOT, DD, HIDDEN, 2);
    {
        size_t n = (size_t)RTOT * HIDDEN;
        ffn_silu_split<<<(unsigned)((n/2 + 255)/256), 256>>>(part, ah, al);
    }
    // w2: split-K=8, generic reduce
    {
        size_t perW = (size_t)RTOT * DD;
        hgemm<<<dim3(DD/BN, MTILES_TOT, 8), 256, GEMM_SMEM>>>(
            ah, al, whw2, wlw2, part, RTOT, HIDDEN, DD, 8);
        reduceN_kernel<<<(unsigned)((perW/4 + 255)/256), 256>>>(part, outrows, 8, perW);
    }
    // 12. scatter
    scatter_out<<<BB*SS, 256>>>(outrows, rank, out);
}